// round 1
// baseline (speedup 1.0000x reference)
#include <cuda_runtime.h>
#include <math.h>

// ---------------- static scratch (no allocations allowed) ----------------
// Largest intermediate: [T*N=1024, 32, 32, 32] = 33,554,432 floats (134 MB)
__device__ float g_bufA[33554432];
__device__ float g_bufB[33554432];
__device__ float g_conv[33554432];
__device__ double g_sum[128];
__device__ double g_sumsq[128];
__device__ float g_inv[128];
__device__ float g_shift[128];

// ---------------- direct 3x3 conv, pad=1, stride=1 ----------------
// Block: (image m, row-strip of RPB rows, CO_BLK output channels)
// Thread: 4 pixels (along W) x 8 output channels = 32 accumulators
template<int CIN,int COUT,int H,int W,int RPB,int CO_BLK,int CCH,int NT>
__global__ __launch_bounds__(NT) void conv3x3_kernel(
    const float* __restrict__ in, const float* __restrict__ wgt,
    const float* __restrict__ bias, float* __restrict__ out)
{
    constexpr int TH = RPB + 2, TW = W + 2;
    constexpr int IN_FLOATS = CCH * TH * TW;
    constexpr int NCG = CO_BLK / 8;
    extern __shared__ float smem[];
    float* s_in = smem;
    float* s_w  = smem + IN_FLOATS;

    const int m      = blockIdx.x;
    const int row0   = blockIdx.y * RPB;
    const int cobase = blockIdx.z * CO_BLK;
    const int tid = threadIdx.x;
    const int cg  = tid % NCG;
    const int pg  = tid / NCG;
    const int r   = pg / (W / 4);
    const int c0  = (pg % (W / 4)) * 4;

    float acc[4][8];
    #pragma unroll
    for (int p = 0; p < 4; p++)
        #pragma unroll
        for (int q = 0; q < 8; q++) acc[p][q] = 0.f;

    for (int cb = 0; cb < CIN; cb += CCH) {
        // load input tile (with halo, zero-padded at borders)
        for (int e = tid; e < IN_FLOATS; e += NT) {
            int ci = e / (TH * TW); int rem = e % (TH * TW);
            int rr = rem / TW, cc = rem % TW;
            int gr = row0 - 1 + rr, gc = cc - 1;
            float v = 0.f;
            if (gr >= 0 && gr < H && gc >= 0 && gc < W)
                v = in[(((size_t)m * CIN + cb + ci) * H + gr) * W + gc];
            s_in[e] = v;
        }
        // load weights: s_w[ci][tap][co]
        constexpr int W_FLOATS = CCH * 9 * CO_BLK;
        for (int e = tid; e < W_FLOATS; e += NT) {
            int co = e % CO_BLK; int t9 = (e / CO_BLK) % 9; int ci = e / (9 * CO_BLK);
            s_w[e] = wgt[(((size_t)(cobase + co)) * CIN + cb + ci) * 9 + t9];
        }
        __syncthreads();

        for (int ci = 0; ci < CCH; ci++) {
            const float* tin = s_in + ci * TH * TW;
            const float* tw  = s_w  + ci * 9 * CO_BLK + cg * 8;
            #pragma unroll
            for (int kh = 0; kh < 3; kh++) {
                float xv[6];
                const float* rowp = tin + (r + kh) * TW + c0;
                #pragma unroll
                for (int j = 0; j < 6; j++) xv[j] = rowp[j];
                #pragma unroll
                for (int kw = 0; kw < 3; kw++) {
                    const float4 w0 = *(const float4*)(tw + (kh * 3 + kw) * CO_BLK);
                    const float4 w1 = *(const float4*)(tw + (kh * 3 + kw) * CO_BLK + 4);
                    float wv[8] = {w0.x, w0.y, w0.z, w0.w, w1.x, w1.y, w1.z, w1.w};
                    #pragma unroll
                    for (int p = 0; p < 4; p++)
                        #pragma unroll
                        for (int q = 0; q < 8; q++)
                            acc[p][q] += xv[kw + p] * wv[q];
                }
            }
        }
        __syncthreads();
    }

    #pragma unroll
    for (int q = 0; q < 8; q++) {
        int co = cobase + cg * 8 + q;
        float b = bias[co];
        float4 v = make_float4(acc[0][q] + b, acc[1][q] + b, acc[2][q] + b, acc[3][q] + b);
        *(float4*)&out[(((size_t)m * COUT + co) * H + row0 + r) * W + c0] = v;
    }
}

// ---------------- BN stats (training mode, biased var) ----------------
__global__ void zero_stats_kernel(double* s, double* s2)
{
    int i = threadIdx.x;
    if (i < 128) { s[i] = 0.0; s2[i] = 0.0; }
}

__global__ void bn_stats_kernel(const float* __restrict__ x, int M, int C, int HW,
                                double* __restrict__ sum, double* __restrict__ sumsq)
{
    int c  = blockIdx.x;
    int sl = blockIdx.y, NSL = gridDim.y;
    int per = (M + NSL - 1) / NSL;
    int m0 = sl * per;
    int m1 = m0 + per; if (m1 > M) m1 = M;
    long cnt = (long)(m1 - m0) * HW;
    double s = 0.0, s2 = 0.0;
    for (long e = threadIdx.x; e < cnt; e += blockDim.x) {
        int m = m0 + (int)(e / HW);
        int i = (int)(e % HW);
        float v = x[((size_t)m * C + c) * HW + i];
        s += v; s2 += (double)v * (double)v;
    }
    __shared__ double sh_s[256];
    __shared__ double sh_s2[256];
    int tid = threadIdx.x;
    sh_s[tid] = s; sh_s2[tid] = s2;
    __syncthreads();
    for (int off = 128; off > 0; off >>= 1) {
        if (tid < off) { sh_s[tid] += sh_s[tid + off]; sh_s2[tid] += sh_s2[tid + off]; }
        __syncthreads();
    }
    if (tid == 0) {
        atomicAdd(sum + c, sh_s[0]);
        atomicAdd(sumsq + c, sh_s2[0]);
    }
}

__global__ void bn_finalize_kernel(const double* __restrict__ sum, const double* __restrict__ sumsq,
                                   double count, const float* __restrict__ g, const float* __restrict__ be,
                                   float* __restrict__ inv, float* __restrict__ shift, int C)
{
    int c = threadIdx.x;
    if (c < C) {
        double m   = sum[c] / count;
        double var = sumsq[c] / count - m * m;
        double iv  = (double)g[c] / sqrt(var + 1e-5);
        inv[c]   = (float)iv;
        shift[c] = (float)((double)be[c] - m * iv);
    }
}

// ---------------- LIF (TAU=2, th=1, hard reset) ----------------
// x layout [T][N][C][HW] (t-stride = nsite); optional per-channel affine (BN)
__global__ void lif_seq_kernel(const float* __restrict__ x, float* __restrict__ s,
                               const float* __restrict__ inv, const float* __restrict__ shift,
                               int nsite, int chw, int hw)
{
    int idx = blockIdx.x * blockDim.x + threadIdx.x;
    if (idx >= nsite) return;
    float iv = 1.f, sh = 0.f;
    if (inv) { int c = (idx % chw) / hw; iv = inv[c]; sh = shift[c]; }
    float v = 0.f;
    #pragma unroll
    for (int t = 0; t < 8; t++) {
        float y = x[(size_t)t * nsite + idx] * iv + sh;
        v = 0.5f * (v + y);
        float sp = (v >= 1.0f) ? 1.0f : 0.0f;
        s[(size_t)t * nsite + idx] = sp;
        v *= (1.0f - sp);
    }
}

// Layer-1 LIF: input identical across T (read once)
__global__ void lif_bcast_kernel(const float* __restrict__ x, float* __restrict__ s,
                                 const float* __restrict__ inv, const float* __restrict__ shift,
                                 int nsite, int chw, int hw)
{
    int idx = blockIdx.x * blockDim.x + threadIdx.x;
    if (idx >= nsite) return;
    int c = (idx % chw) / hw;
    float y = x[idx] * inv[c] + shift[c];
    float v = 0.f;
    #pragma unroll
    for (int t = 0; t < 8; t++) {
        v = 0.5f * (v + y);
        float sp = (v >= 1.0f) ? 1.0f : 0.0f;
        s[(size_t)t * nsite + idx] = sp;
        v *= (1.0f - sp);
    }
}

// ---------------- 2x2 maxpool, stride 2 ----------------
__global__ void pool_kernel(const float* __restrict__ x, float* __restrict__ y,
                            int n_out, int OH, int OW, int H, int W)
{
    int idx = blockIdx.x * blockDim.x + threadIdx.x;
    if (idx >= n_out) return;
    int ow = idx % OW;
    int oh = (idx / OW) % OH;
    int mc = idx / (OW * OH);
    const float* p = x + ((size_t)mc * H + 2 * oh) * W + 2 * ow;
    float a = fmaxf(p[0], p[1]);
    float b = fmaxf(p[W], p[W + 1]);
    y[idx] = fmaxf(a, b);
}

// ---------------- fc1: [1024,2048] x [128,2048]^T + bias ----------------
__global__ __launch_bounds__(256) void fc1_kernel(const float* __restrict__ A,
                                                  const float* __restrict__ Bw,
                                                  const float* __restrict__ bias,
                                                  float* __restrict__ C)
{
    __shared__ float As[32][64];
    __shared__ float Bs[64][132];
    int tid = threadIdx.x;
    int r0 = blockIdx.x * 32;
    int tx = tid % 32, ty = tid / 32;
    float acc[4][4];
    #pragma unroll
    for (int i = 0; i < 4; i++)
        #pragma unroll
        for (int j = 0; j < 4; j++) acc[i][j] = 0.f;

    for (int k0 = 0; k0 < 2048; k0 += 64) {
        #pragma unroll
        for (int l = 0; l < 8; l++) {
            int e = tid + l * 256;
            int rr = e >> 6, kk = e & 63;
            As[rr][kk] = A[(size_t)(r0 + rr) * 2048 + k0 + kk];
        }
        #pragma unroll
        for (int l = 0; l < 32; l++) {
            int e = tid + l * 256;
            int kk = e & 63, oo = e >> 6;
            Bs[kk][oo] = Bw[(size_t)oo * 2048 + k0 + kk];
        }
        __syncthreads();
        for (int kk = 0; kk < 64; kk++) {
            float a[4];
            #pragma unroll
            for (int i = 0; i < 4; i++) a[i] = As[ty * 4 + i][kk];
            float4 bv = *(const float4*)&Bs[kk][tx * 4];
            float b[4] = {bv.x, bv.y, bv.z, bv.w};
            #pragma unroll
            for (int i = 0; i < 4; i++)
                #pragma unroll
                for (int j = 0; j < 4; j++)
                    acc[i][j] += a[i] * b[j];
        }
        __syncthreads();
    }
    #pragma unroll
    for (int i = 0; i < 4; i++)
        #pragma unroll
        for (int j = 0; j < 4; j++)
            C[(size_t)(r0 + ty * 4 + i) * 128 + tx * 4 + j] = acc[i][j] + bias[tx * 4 + j];
}

// ---------------- fc2 + LIF + mean over T, fused ----------------
// h layout [T][N][128]; block per n; warp per output o (10 warps)
__global__ __launch_bounds__(320) void fc2_lif_mean_kernel(const float* __restrict__ h,
                                                           const float* __restrict__ w2,
                                                           const float* __restrict__ b2,
                                                           float* __restrict__ out)
{
    int n = blockIdx.x;
    int o = threadIdx.x / 32;
    int lane = threadIdx.x % 32;
    float w[4];
    #pragma unroll
    for (int j = 0; j < 4; j++) w[j] = w2[o * 128 + lane * 4 + j];
    float bb = b2[o];
    float v = 0.f, accum = 0.f;
    #pragma unroll
    for (int t = 0; t < 8; t++) {
        const float* hp = h + (size_t)t * 16384 + (size_t)n * 128 + lane * 4;
        float p = 0.f;
        #pragma unroll
        for (int j = 0; j < 4; j++) p += hp[j] * w[j];
        #pragma unroll
        for (int off = 16; off > 0; off >>= 1)
            p += __shfl_xor_sync(0xffffffffu, p, off);
        float y = p + bb;
        v = 0.5f * (v + y);
        float sp = (v >= 1.0f) ? 1.0f : 0.0f;
        v *= (1.0f - sp);
        accum += sp;
    }
    if (lane == 0) out[n * 10 + o] = accum * 0.125f;
}

// ---------------- host orchestration ----------------
static void run_bn(const float* cv, int M, int C, int HW,
                   const float* g, const float* be,
                   double* sum, double* sumsq, float* inv, float* shift)
{
    zero_stats_kernel<<<1, 128>>>(sum, sumsq);
    dim3 gs(C, 32);
    bn_stats_kernel<<<gs, 256>>>(cv, M, C, HW, sum, sumsq);
    bn_finalize_kernel<<<1, C>>>(sum, sumsq, (double)M * (double)HW, g, be, inv, shift, C);
}

extern "C" void kernel_launch(void* const* d_in, const int* in_sizes, int n_in,
                              void* d_out, int out_size)
{
    const float* x = (const float*)d_in[0];
    const float* w[6]; const float* b[6]; const float* gm[6]; const float* be[6];
    for (int i = 0; i < 6; i++) {
        w[i]  = (const float*)d_in[1 + 4 * i];
        b[i]  = (const float*)d_in[2 + 4 * i];
        gm[i] = (const float*)d_in[3 + 4 * i];
        be[i] = (const float*)d_in[4 + 4 * i];
    }
    const float* fc1_w = (const float*)d_in[25];
    const float* fc1_b = (const float*)d_in[26];
    const float* fc2_w = (const float*)d_in[27];
    const float* fc2_b = (const float*)d_in[28];
    float* out = (float*)d_out;

    float *bufA, *bufB, *conv, *inv, *shift;
    double *sum, *sumsq;
    cudaGetSymbolAddress((void**)&bufA, g_bufA);
    cudaGetSymbolAddress((void**)&bufB, g_bufB);
    cudaGetSymbolAddress((void**)&conv, g_conv);
    cudaGetSymbolAddress((void**)&sum, g_sum);
    cudaGetSymbolAddress((void**)&sumsq, g_sumsq);
    cudaGetSymbolAddress((void**)&inv, g_inv);
    cudaGetSymbolAddress((void**)&shift, g_shift);

    // conv kernel instances + dynamic smem sizes
    auto k1 = conv3x3_kernel<3, 32, 32, 32, 8, 32, 3, 256>;
    auto k2 = conv3x3_kernel<32, 32, 32, 32, 8, 32, 32, 256>;
    auto k3 = conv3x3_kernel<32, 64, 16, 16, 8, 64, 32, 256>;
    auto k4 = conv3x3_kernel<64, 64, 16, 16, 8, 64, 32, 256>;
    auto k5 = conv3x3_kernel<64, 128, 8, 8, 8, 64, 32, 128>;
    auto k6 = conv3x3_kernel<128, 128, 8, 8, 8, 64, 32, 128>;
    const int sm1 = (3 * 10 * 34 + 3 * 9 * 32) * 4;     // 7536
    const int sm2 = (32 * 10 * 34 + 32 * 9 * 32) * 4;   // 80384
    const int sm3 = (32 * 10 * 18 + 32 * 9 * 64) * 4;   // 96768
    const int sm5 = (32 * 10 * 10 + 32 * 9 * 64) * 4;   // 86528
    cudaFuncSetAttribute((const void*)k2, cudaFuncAttributeMaxDynamicSharedMemorySize, sm2);
    cudaFuncSetAttribute((const void*)k3, cudaFuncAttributeMaxDynamicSharedMemorySize, sm3);
    cudaFuncSetAttribute((const void*)k4, cudaFuncAttributeMaxDynamicSharedMemorySize, sm3);
    cudaFuncSetAttribute((const void*)k5, cudaFuncAttributeMaxDynamicSharedMemorySize, sm5);
    cudaFuncSetAttribute((const void*)k6, cudaFuncAttributeMaxDynamicSharedMemorySize, sm5);

    const int N = 128, M = 1024; // M = T*N

    // ---- Layer 1 (input identical across T: conv once over N images) ----
    k1<<<dim3(N, 4, 1), 256, sm1>>>(x, w[0], b[0], conv);
    run_bn(conv, N, 32, 1024, gm[0], be[0], sum, sumsq, inv, shift);
    {
        int nsite = N * 32 * 1024;
        lif_bcast_kernel<<<(nsite + 255) / 256, 256>>>(conv, bufA, inv, shift, nsite, 32 * 1024, 1024);
    }

    // ---- Layer 2 ----
    k2<<<dim3(M, 4, 1), 256, sm2>>>(bufA, w[1], b[1], conv);
    run_bn(conv, M, 32, 1024, gm[1], be[1], sum, sumsq, inv, shift);
    {
        int nsite = N * 32 * 1024;
        lif_seq_kernel<<<(nsite + 255) / 256, 256>>>(conv, bufB, inv, shift, nsite, 32 * 1024, 1024);
    }
    // pool [1024,32,32,32] -> [1024,32,16,16]
    {
        int n_out = M * 32 * 16 * 16;
        pool_kernel<<<(n_out + 255) / 256, 256>>>(bufB, bufA, n_out, 16, 16, 32, 32);
    }

    // ---- Layer 3 ----
    k3<<<dim3(M, 2, 1), 256, sm3>>>(bufA, w[2], b[2], conv);
    run_bn(conv, M, 64, 256, gm[2], be[2], sum, sumsq, inv, shift);
    {
        int nsite = N * 64 * 256;
        lif_seq_kernel<<<(nsite + 255) / 256, 256>>>(conv, bufB, inv, shift, nsite, 64 * 256, 256);
    }

    // ---- Layer 4 ----
    k4<<<dim3(M, 2, 1), 256, sm3>>>(bufB, w[3], b[3], conv);
    run_bn(conv, M, 64, 256, gm[3], be[3], sum, sumsq, inv, shift);
    {
        int nsite = N * 64 * 256;
        lif_seq_kernel<<<(nsite + 255) / 256, 256>>>(conv, bufA, inv, shift, nsite, 64 * 256, 256);
    }
    // pool [1024,64,16,16] -> [1024,64,8,8]
    {
        int n_out = M * 64 * 8 * 8;
        pool_kernel<<<(n_out + 255) / 256, 256>>>(bufA, bufB, n_out, 8, 8, 16, 16);
    }

    // ---- Layer 5 ----
    k5<<<dim3(M, 1, 2), 128, sm5>>>(bufB, w[4], b[4], conv);
    run_bn(conv, M, 128, 64, gm[4], be[4], sum, sumsq, inv, shift);
    {
        int nsite = N * 128 * 64;
        lif_seq_kernel<<<(nsite + 255) / 256, 256>>>(conv, bufA, inv, shift, nsite, 128 * 64, 64);
    }

    // ---- Layer 6 ----
    k6<<<dim3(M, 1, 2), 128, sm5>>>(bufA, w[5], b[5], conv);
    run_bn(conv, M, 128, 64, gm[5], be[5], sum, sumsq, inv, shift);
    {
        int nsite = N * 128 * 64;
        lif_seq_kernel<<<(nsite + 255) / 256, 256>>>(conv, bufB, inv, shift, nsite, 128 * 64, 64);
    }
    // pool [1024,128,8,8] -> [1024,128,4,4] == flatten [1024,2048]
    {
        int n_out = M * 128 * 4 * 4;
        pool_kernel<<<(n_out + 255) / 256, 256>>>(bufB, bufA, n_out, 4, 4, 8, 8);
    }

    // ---- fc1 + LIF ----
    fc1_kernel<<<32, 256>>>(bufA, fc1_w, fc1_b, conv); // conv reused as [1024,128]
    {
        int nsite = N * 128;
        lif_seq_kernel<<<(nsite + 255) / 256, 256>>>(conv, bufB, (const float*)0, (const float*)0,
                                                     nsite, 128, 1);
    }

    // ---- fc2 + LIF + mean ----
    fc2_lif_mean_kernel<<<N, 320>>>(bufB, fc2_w, fc2_b, out);
}

// round 3
// speedup vs baseline: 2.2100x; 2.2100x over previous
#include <cuda_runtime.h>
#include <math.h>
#include <stdint.h>

// ---------------- static scratch (no allocations allowed) ----------------
__device__ float g_bufA[33554432];
__device__ float g_bufB[33554432];
__device__ float g_conv[33554432];
__device__ float g_wpk[1048576];
__device__ double g_sum[128];
__device__ double g_sumsq[128];
__device__ float g_inv[128];
__device__ float g_shift[128];

// ---------------- weight packing into mma-fragment order ----------------
// Layout: [chunk ch = tap*CCH + c32][k8 step s:4][tile j:COUT/8][lane:32][4]
// lane -> (g = lane>>2, t = lane&3); 4 floats = {b0hi, b1hi, b0lo, b1lo}
//   b0: W[n = 8j+g][k = s*8 + t]      (k within the 32-chan chunk)
//   b1: W[n = 8j+g][k = s*8 + t + 4]
__global__ void pack_w_kernel(const float* __restrict__ w, float* __restrict__ bpk,
                              int CIN, int COUT) {
    int total = 18 * CIN * COUT;            // NCH * 64*COUT floats
    int idx = blockIdx.x * 256 + threadIdx.x;
    if (idx >= total) return;
    int f    = idx & 3;
    int lane = (idx >> 2) & 31;
    int j    = (idx >> 7) % (COUT / 8);
    int s    = (idx / (32 * COUT)) & 3;
    int ch   = idx / (128 * COUT);
    int g = lane >> 2, t = lane & 3;
    int CCH = CIN / 32;
    int tap = ch / CCH, c32 = ch % CCH;
    int n  = 8 * j + g;
    int kk = s * 8 + t + ((f & 1) ? 4 : 0);
    int ci = c32 * 32 + kk;
    float v = w[((size_t)n * CIN + ci) * 9 + tap];
    uint32_t hb;
    asm("cvt.rna.tf32.f32 %0, %1;" : "=r"(hb) : "f"(v));
    float hi = __uint_as_float(hb);
    bpk[idx] = (f >> 1) ? (v - hi) : hi;
}

// fc1 weight permutation: NCHW-flatten -> NHWC-flatten of the [128,4,4] map
__global__ void permute_fc1_kernel(const float* __restrict__ w, float* __restrict__ wp) {
    int idx = blockIdx.x * 256 + threadIdx.x;
    if (idx >= 128 * 2048) return;
    int o = idx / 2048, k = idx % 2048;   // k = yx*128 + c
    int c = k % 128, yx = k / 128;
    wp[idx] = w[o * 2048 + c * 16 + yx];
}

// ---------------- mma.sync tf32 implicit GEMM 3x3 conv (NHWC) ----------------
// in: spikes NHWC [M][H][W][CIN]; bpk: packed split weights; out: NHWC conv+bias
template<int CIN, int COUT, int H, int W>
__global__ __launch_bounds__(256) void conv_mma(const float* __restrict__ in,
                                                const float* __restrict__ bpk,
                                                const float* __restrict__ bias,
                                                float* __restrict__ out)
{
    constexpr int HW = H * W;
    constexpr int CCH = CIN / 32;
    constexpr int NCH = 9 * CCH;
    constexpr int NTILE = COUT / 8;
    constexpr int A_FLOATS = 128 * 36;          // padded stride 36
    constexpr int B_FLOATS = 64 * COUT;         // one chunk, fragment order

    extern __shared__ float smem[];
    float*  As  = smem;
    float4* Bs4 = (float4*)(smem + A_FLOATS);

    const int tid  = threadIdx.x;
    const int wid  = tid >> 5;
    const int lane = tid & 31;
    const int g = lane >> 2, t = lane & 3;
    const int p0 = blockIdx.x * 128;

    float acc[NTILE][4];
    #pragma unroll
    for (int j = 0; j < NTILE; j++)
        #pragma unroll
        for (int q = 0; q < 4; q++) acc[j][q] = 0.f;

    for (int ch = 0; ch < NCH; ch++) {
        if (ch > 0) __syncthreads();
        // ---- load A chunk: 128 pixels x 32 channels (im2col gather) ----
        {
            int tap = ch / CCH, c32 = ch % CCH;
            int ky = tap / 3 - 1, kx = tap % 3 - 1;
            #pragma unroll
            for (int it = 0; it < 4; it++) {
                int lin = it * 256 + tid;
                int ml = lin >> 3, j4 = lin & 7;
                int P = p0 + ml;
                int img = P / HW, pix = P % HW;
                int y = pix / W, x = pix % W;
                int yy = y + ky, xx = x + kx;
                float4 v = make_float4(0.f, 0.f, 0.f, 0.f);
                if ((unsigned)yy < (unsigned)H && (unsigned)xx < (unsigned)W)
                    v = *(const float4*)&in[(((size_t)img * H + yy) * W + xx) * CIN + c32 * 32 + j4 * 4];
                *(float4*)&As[ml * 36 + j4 * 4] = v;
            }
        }
        // ---- load B chunk (already fragment-ordered, linear copy) ----
        {
            const float4* src = (const float4*)(bpk + (size_t)ch * B_FLOATS);
            constexpr int NV = B_FLOATS / 4;
            #pragma unroll
            for (int i = tid; i < NV; i += 256) Bs4[i] = src[i];
        }
        __syncthreads();

        // ---- compute: 4 k8 steps ----
        const int m = wid * 16;
        #pragma unroll
        for (int s = 0; s < 4; s++) {
            uint32_t a0 = __float_as_uint(As[(m + g) * 36 + s * 8 + t]);
            uint32_t a1 = __float_as_uint(As[(m + 8 + g) * 36 + s * 8 + t]);
            uint32_t a2 = __float_as_uint(As[(m + g) * 36 + s * 8 + t + 4]);
            uint32_t a3 = __float_as_uint(As[(m + 8 + g) * 36 + s * 8 + t + 4]);
            #pragma unroll
            for (int j = 0; j < NTILE; j++) {
                float4 bf = Bs4[(s * NTILE + j) * 32 + lane];
                uint32_t b0h = __float_as_uint(bf.x), b1h = __float_as_uint(bf.y);
                uint32_t b0l = __float_as_uint(bf.z), b1l = __float_as_uint(bf.w);
                asm("mma.sync.aligned.m16n8k8.row.col.f32.tf32.tf32.f32 "
                    "{%0,%1,%2,%3}, {%4,%5,%6,%7}, {%8,%9}, {%0,%1,%2,%3};"
                    : "+f"(acc[j][0]), "+f"(acc[j][1]), "+f"(acc[j][2]), "+f"(acc[j][3])
                    : "r"(a0), "r"(a1), "r"(a2), "r"(a3), "r"(b0h), "r"(b1h));
                asm("mma.sync.aligned.m16n8k8.row.col.f32.tf32.tf32.f32 "
                    "{%0,%1,%2,%3}, {%4,%5,%6,%7}, {%8,%9}, {%0,%1,%2,%3};"
                    : "+f"(acc[j][0]), "+f"(acc[j][1]), "+f"(acc[j][2]), "+f"(acc[j][3])
                    : "r"(a0), "r"(a1), "r"(a2), "r"(a3), "r"(b0l), "r"(b1l));
            }
        }
    }

    // ---- epilogue: bias + store (NHWC) ----
    const int row0 = p0 + wid * 16 + g;
    #pragma unroll
    for (int j = 0; j < NTILE; j++) {
        int col = 8 * j + 2 * t;
        float2 bb = *(const float2*)&bias[col];
        float2 v0 = make_float2(acc[j][0] + bb.x, acc[j][1] + bb.y);
        float2 v1 = make_float2(acc[j][2] + bb.x, acc[j][3] + bb.y);
        *(float2*)&out[(size_t)row0 * COUT + col] = v0;
        *(float2*)&out[(size_t)(row0 + 8) * COUT + col] = v1;
    }
}

// ---------------- layer-1 direct fp32 conv (CIN=3), NCHW in -> NHWC out ----------------
template<int CIN, int COUT, int H, int W, int RPB, int CO_BLK, int CCH, int NT>
__global__ __launch_bounds__(NT) void conv3x3_kernel(
    const float* __restrict__ in, const float* __restrict__ wgt,
    const float* __restrict__ bias, float* __restrict__ out)
{
    constexpr int TH = RPB + 2, TW = W + 2;
    constexpr int IN_FLOATS = CCH * TH * TW;
    constexpr int NCG = CO_BLK / 8;
    extern __shared__ float smemf[];
    float* s_in = smemf;
    float* s_w  = smemf + IN_FLOATS;

    const int m = blockIdx.x;
    const int row0 = blockIdx.y * RPB;
    const int cobase = blockIdx.z * CO_BLK;
    const int tid = threadIdx.x;
    const int cg = tid % NCG;
    const int pg = tid / NCG;
    const int r = pg / (W / 4);
    const int c0 = (pg % (W / 4)) * 4;

    float acc[4][8];
    #pragma unroll
    for (int p = 0; p < 4; p++)
        #pragma unroll
        for (int q = 0; q < 8; q++) acc[p][q] = 0.f;

    for (int cb = 0; cb < CIN; cb += CCH) {
        for (int e = tid; e < IN_FLOATS; e += NT) {
            int ci = e / (TH * TW); int rem = e % (TH * TW);
            int rr = rem / TW, cc = rem % TW;
            int gr = row0 - 1 + rr, gc = cc - 1;
            float v = 0.f;
            if (gr >= 0 && gr < H && gc >= 0 && gc < W)
                v = in[(((size_t)m * CIN + cb + ci) * H + gr) * W + gc];
            s_in[e] = v;
        }
        constexpr int W_FLOATS = CCH * 9 * CO_BLK;
        for (int e = tid; e < W_FLOATS; e += NT) {
            int co = e % CO_BLK; int t9 = (e / CO_BLK) % 9; int ci = e / (9 * CO_BLK);
            s_w[e] = wgt[(((size_t)(cobase + co)) * CIN + cb + ci) * 9 + t9];
        }
        __syncthreads();

        for (int ci = 0; ci < CCH; ci++) {
            const float* tin = s_in + ci * TH * TW;
            const float* tw  = s_w  + ci * 9 * CO_BLK + cg * 8;
            #pragma unroll
            for (int kh = 0; kh < 3; kh++) {
                float xv[6];
                const float* rowp = tin + (r + kh) * TW + c0;
                #pragma unroll
                for (int j = 0; j < 6; j++) xv[j] = rowp[j];
                #pragma unroll
                for (int kw = 0; kw < 3; kw++) {
                    const float4 w0 = *(const float4*)(tw + (kh * 3 + kw) * CO_BLK);
                    const float4 w1 = *(const float4*)(tw + (kh * 3 + kw) * CO_BLK + 4);
                    float wv[8] = {w0.x, w0.y, w0.z, w0.w, w1.x, w1.y, w1.z, w1.w};
                    #pragma unroll
                    for (int p = 0; p < 4; p++)
                        #pragma unroll
                        for (int q = 0; q < 8; q++)
                            acc[p][q] += xv[kw + p] * wv[q];
                }
            }
        }
        __syncthreads();
    }

    float bq[8];
    #pragma unroll
    for (int q = 0; q < 8; q++) bq[q] = bias[cobase + cg * 8 + q];
    #pragma unroll
    for (int p = 0; p < 4; p++) {
        float* op = &out[(((size_t)m * H + row0 + r) * W + c0 + p) * COUT + cobase + cg * 8];
        float4 v0 = make_float4(acc[p][0] + bq[0], acc[p][1] + bq[1], acc[p][2] + bq[2], acc[p][3] + bq[3]);
        float4 v1 = make_float4(acc[p][4] + bq[4], acc[p][5] + bq[5], acc[p][6] + bq[6], acc[p][7] + bq[7]);
        *(float4*)op = v0;
        *(float4*)(op + 4) = v1;
    }
}

// ---------------- BN stats (NHWC, training mode, biased var) ----------------
__global__ void zero_stats_kernel(double* s, double* s2)
{
    int i = threadIdx.x;
    if (i < 128) { s[i] = 0.0; s2[i] = 0.0; }
}

__global__ void bn_stats_nhwc(const float* __restrict__ x, long npix, int C,
                              double* __restrict__ sum, double* __restrict__ sumsq)
{
    int tid = threadIdx.x;
    int c = tid % C, g = tid / C;
    int G = blockDim.x / C;
    double s = 0.0, s2 = 0.0;
    for (long p = (long)blockIdx.x * G + g; p < npix; p += (long)gridDim.x * G) {
        float v = x[p * C + c];
        s += v; s2 += (double)v * (double)v;
    }
    __shared__ double sh[256], sh2[256];
    sh[tid] = s; sh2[tid] = s2;
    __syncthreads();
    for (int st = G / 2; st > 0; st >>= 1) {
        if (g < st) { sh[tid] += sh[tid + st * C]; sh2[tid] += sh2[tid + st * C]; }
        __syncthreads();
    }
    if (g == 0) {
        atomicAdd(sum + c, sh[tid]);
        atomicAdd(sumsq + c, sh2[tid]);
    }
}

__global__ void bn_finalize_kernel(const double* __restrict__ sum, const double* __restrict__ sumsq,
                                   double count, const float* __restrict__ g, const float* __restrict__ be,
                                   float* __restrict__ inv, float* __restrict__ shift, int C)
{
    int c = threadIdx.x;
    if (c < C) {
        double m   = sum[c] / count;
        double var = sumsq[c] / count - m * m;
        double iv  = (double)g[c] / sqrt(var + 1e-5);
        inv[c]   = (float)iv;
        shift[c] = (float)((double)be[c] - m * iv);
    }
}

// ---------------- LIF (TAU=2, th=1, hard reset), NHWC ----------------
__global__ void lif_seq_kernel(const float* __restrict__ x, float* __restrict__ s,
                               const float* __restrict__ inv, const float* __restrict__ shift,
                               int nsite, int C)
{
    int idx = blockIdx.x * blockDim.x + threadIdx.x;
    if (idx >= nsite) return;
    float iv = 1.f, sh = 0.f;
    if (inv) { int c = idx % C; iv = inv[c]; sh = shift[c]; }
    float v = 0.f;
    #pragma unroll
    for (int t = 0; t < 8; t++) {
        float y = x[(size_t)t * nsite + idx] * iv + sh;
        v = 0.5f * (v + y);
        float sp = (v >= 1.0f) ? 1.0f : 0.0f;
        s[(size_t)t * nsite + idx] = sp;
        v *= (1.0f - sp);
    }
}

__global__ void lif_bcast_kernel(const float* __restrict__ x, float* __restrict__ s,
                                 const float* __restrict__ inv, const float* __restrict__ shift,
                                 int nsite, int C)
{
    int idx = blockIdx.x * blockDim.x + threadIdx.x;
    if (idx >= nsite) return;
    int c = idx % C;
    float y = x[idx] * inv[c] + shift[c];
    float v = 0.f;
    #pragma unroll
    for (int t = 0; t < 8; t++) {
        v = 0.5f * (v + y);
        float sp = (v >= 1.0f) ? 1.0f : 0.0f;
        s[(size_t)t * nsite + idx] = sp;
        v *= (1.0f - sp);
    }
}

// ---------------- 2x2 maxpool, stride 2, NHWC ----------------
__global__ void pool_nhwc(const float* __restrict__ x, float* __restrict__ y,
                          int n_out, int OH, int OW, int C)
{
    int idx = blockIdx.x * blockDim.x + threadIdx.x;
    if (idx >= n_out) return;
    int c = idx % C;
    int r = idx / C;
    int ox = r % OW;
    int r2 = r / OW;
    int oy = r2 % OH;
    int m = r2 / OH;
    int Wi = OW * 2;
    const float* p = x + (((size_t)m * (OH * 2) + 2 * oy) * Wi + 2 * ox) * C + c;
    float a = fmaxf(p[0], p[C]);
    float b = fmaxf(p[(size_t)Wi * C], p[(size_t)Wi * C + C]);
    y[idx] = fmaxf(a, b);
}

// ---------------- fc1: [1024,2048] x [128,2048]^T + bias ----------------
__global__ __launch_bounds__(256) void fc1_kernel(const float* __restrict__ A,
                                                  const float* __restrict__ Bw,
                                                  const float* __restrict__ bias,
                                                  float* __restrict__ C)
{
    __shared__ float As[32][64];
    __shared__ float Bs[64][132];
    int tid = threadIdx.x;
    int r0 = blockIdx.x * 32;
    int tx = tid % 32, ty = tid / 32;
    float acc[4][4];
    #pragma unroll
    for (int i = 0; i < 4; i++)
        #pragma unroll
        for (int j = 0; j < 4; j++) acc[i][j] = 0.f;

    for (int k0 = 0; k0 < 2048; k0 += 64) {
        #pragma unroll
        for (int l = 0; l < 8; l++) {
            int e = tid + l * 256;
            int rr = e >> 6, kk = e & 63;
            As[rr][kk] = A[(size_t)(r0 + rr) * 2048 + k0 + kk];
        }
        #pragma unroll
        for (int l = 0; l < 32; l++) {
            int e = tid + l * 256;
            int kk = e & 63, oo = e >> 6;
            Bs[kk][oo] = Bw[(size_t)oo * 2048 + k0 + kk];
        }
        __syncthreads();
        for (int kk = 0; kk < 64; kk++) {
            float a[4];
            #pragma unroll
            for (int i = 0; i < 4; i++) a[i] = As[ty * 4 + i][kk];
            float4 bv = *(const float4*)&Bs[kk][tx * 4];
            float b[4] = {bv.x, bv.y, bv.z, bv.w};
            #pragma unroll
            for (int i = 0; i < 4; i++)
                #pragma unroll
                for (int j = 0; j < 4; j++)
                    acc[i][j] += a[i] * b[j];
        }
        __syncthreads();
    }
    #pragma unroll
    for (int i = 0; i < 4; i++)
        #pragma unroll
        for (int j = 0; j < 4; j++)
            C[(size_t)(r0 + ty * 4 + i) * 128 + tx * 4 + j] = acc[i][j] + bias[tx * 4 + j];
}

// ---------------- fc2 + LIF + mean over T, fused ----------------
__global__ __launch_bounds__(320) void fc2_lif_mean_kernel(const float* __restrict__ h,
                                                           const float* __restrict__ w2,
                                                           const float* __restrict__ b2,
                                                           float* __restrict__ out)
{
    int n = blockIdx.x;
    int o = threadIdx.x / 32;
    int lane = threadIdx.x % 32;
    float w[4];
    #pragma unroll
    for (int j = 0; j < 4; j++) w[j] = w2[o * 128 + lane * 4 + j];
    float bb = b2[o];
    float v = 0.f, accum = 0.f;
    #pragma unroll
    for (int t = 0; t < 8; t++) {
        const float* hp = h + (size_t)t * 16384 + (size_t)n * 128 + lane * 4;
        float p = 0.f;
        #pragma unroll
        for (int j = 0; j < 4; j++) p += hp[j] * w[j];
        #pragma unroll
        for (int off = 16; off > 0; off >>= 1)
            p += __shfl_xor_sync(0xffffffffu, p, off);
        float y = p + bb;
        v = 0.5f * (v + y);
        float sp = (v >= 1.0f) ? 1.0f : 0.0f;
        v *= (1.0f - sp);
        accum += sp;
    }
    if (lane == 0) out[n * 10 + o] = accum * 0.125f;
}

// ---------------- host orchestration ----------------
static void run_bn(const float* cv, long npix, int C,
                   const float* g, const float* be,
                   double* sum, double* sumsq, float* inv, float* shift)
{
    zero_stats_kernel<<<1, 128>>>(sum, sumsq);
    bn_stats_nhwc<<<512, 256>>>(cv, npix, C, sum, sumsq);
    bn_finalize_kernel<<<1, C>>>(sum, sumsq, (double)npix, g, be, inv, shift, C);
}

extern "C" void kernel_launch(void* const* d_in, const int* in_sizes, int n_in,
                              void* d_out, int out_size)
{
    const float* x = (const float*)d_in[0];
    const float* w[6]; const float* b[6]; const float* gm[6]; const float* be[6];
    for (int i = 0; i < 6; i++) {
        w[i]  = (const float*)d_in[1 + 4 * i];
        b[i]  = (const float*)d_in[2 + 4 * i];
        gm[i] = (const float*)d_in[3 + 4 * i];
        be[i] = (const float*)d_in[4 + 4 * i];
    }
    const float* fc1_w = (const float*)d_in[25];
    const float* fc1_b = (const float*)d_in[26];
    const float* fc2_w = (const float*)d_in[27];
    const float* fc2_b = (const float*)d_in[28];
    float* out = (float*)d_out;

    float *bufA, *bufB, *conv, *inv, *shift, *wpk;
    double *sum, *sumsq;
    cudaGetSymbolAddress((void**)&bufA, g_bufA);
    cudaGetSymbolAddress((void**)&bufB, g_bufB);
    cudaGetSymbolAddress((void**)&conv, g_conv);
    cudaGetSymbolAddress((void**)&wpk, g_wpk);
    cudaGetSymbolAddress((void**)&sum, g_sum);
    cudaGetSymbolAddress((void**)&sumsq, g_sumsq);
    cudaGetSymbolAddress((void**)&inv, g_inv);
    cudaGetSymbolAddress((void**)&shift, g_shift);

    // packed-weight offsets (floats): 18*CIN*COUT each
    float* wp2 = wpk;             // 18432
    float* wp3 = wpk + 18432;     // 36864
    float* wp4 = wpk + 55296;     // 73728
    float* wp5 = wpk + 129024;    // 147456
    float* wp6 = wpk + 276480;    // 294912
    float* wfc = wpk + 571392;    // 262144

    // ---- weight prep ----
    pack_w_kernel<<<(18 * 32 * 32 + 255) / 256, 256>>>(w[1], wp2, 32, 32);
    pack_w_kernel<<<(18 * 32 * 64 + 255) / 256, 256>>>(w[2], wp3, 32, 64);
    pack_w_kernel<<<(18 * 64 * 64 + 255) / 256, 256>>>(w[3], wp4, 64, 64);
    pack_w_kernel<<<(18 * 64 * 128 + 255) / 256, 256>>>(w[4], wp5, 64, 128);
    pack_w_kernel<<<(18 * 128 * 128 + 255) / 256, 256>>>(w[5], wp6, 128, 128);
    permute_fc1_kernel<<<(128 * 2048 + 255) / 256, 256>>>(fc1_w, wfc);

    // ---- kernel instances + smem attrs ----
    auto k1 = conv3x3_kernel<3, 32, 32, 32, 8, 32, 3, 256>;
    const int sm1 = (3 * 10 * 34 + 3 * 9 * 32) * 4;

    auto g2 = conv_mma<32, 32, 32, 32>;
    auto g3 = conv_mma<32, 64, 16, 16>;
    auto g4 = conv_mma<64, 64, 16, 16>;
    auto g5 = conv_mma<64, 128, 8, 8>;
    auto g6 = conv_mma<128, 128, 8, 8>;
    const int smg2  = (128 * 36 + 64 * 32) * 4;    // 26624
    const int smg34 = (128 * 36 + 64 * 64) * 4;    // 34816
    const int smg56 = (128 * 36 + 64 * 128) * 4;   // 51200
    cudaFuncSetAttribute((const void*)g2, cudaFuncAttributeMaxDynamicSharedMemorySize, smg2);
    cudaFuncSetAttribute((const void*)g3, cudaFuncAttributeMaxDynamicSharedMemorySize, smg34);
    cudaFuncSetAttribute((const void*)g4, cudaFuncAttributeMaxDynamicSharedMemorySize, smg34);
    cudaFuncSetAttribute((const void*)g5, cudaFuncAttributeMaxDynamicSharedMemorySize, smg56);
    cudaFuncSetAttribute((const void*)g6, cudaFuncAttributeMaxDynamicSharedMemorySize, smg56);

    const int N = 128, M = 1024;  // M = T*N

    // ---- Layer 1 (input identical across T: conv once over N images), NHWC out ----
    k1<<<dim3(N, 4, 1), 256, sm1>>>(x, w[0], b[0], conv);
    run_bn(conv, (long)N * 1024, 32, gm[0], be[0], sum, sumsq, inv, shift);
    {
        int nsite = N * 1024 * 32;
        lif_bcast_kernel<<<(nsite + 255) / 256, 256>>>(conv, bufA, inv, shift, nsite, 32);
    }

    // ---- Layer 2 ----
    g2<<<M * 1024 / 128, 256, smg2>>>(bufA, wp2, b[1], conv);
    run_bn(conv, (long)M * 1024, 32, gm[1], be[1], sum, sumsq, inv, shift);
    {
        int nsite = N * 1024 * 32;
        lif_seq_kernel<<<(nsite + 255) / 256, 256>>>(conv, bufB, inv, shift, nsite, 32);
    }
    {
        int n_out = M * 32 * 16 * 16;
        pool_nhwc<<<(n_out + 255) / 256, 256>>>(bufB, bufA, n_out, 16, 16, 32);
    }

    // ---- Layer 3 ----
    g3<<<M * 256 / 128, 256, smg34>>>(bufA, wp3, b[2], conv);
    run_bn(conv, (long)M * 256, 64, gm[2], be[2], sum, sumsq, inv, shift);
    {
        int nsite = N * 256 * 64;
        lif_seq_kernel<<<(nsite + 255) / 256, 256>>>(conv, bufB, inv, shift, nsite, 64);
    }

    // ---- Layer 4 ----
    g4<<<M * 256 / 128, 256, smg34>>>(bufB, wp4, b[3], conv);
    run_bn(conv, (long)M * 256, 64, gm[3], be[3], sum, sumsq, inv, shift);
    {
        int nsite = N * 256 * 64;
        lif_seq_kernel<<<(nsite + 255) / 256, 256>>>(conv, bufA, inv, shift, nsite, 64);
    }
    {
        int n_out = M * 64 * 8 * 8;
        pool_nhwc<<<(n_out + 255) / 256, 256>>>(bufA, bufB, n_out, 8, 8, 64);
    }

    // ---- Layer 5 ----
    g5<<<M * 64 / 128, 256, smg56>>>(bufB, wp5, b[4], conv);
    run_bn(conv, (long)M * 64, 128, gm[4], be[4], sum, sumsq, inv, shift);
    {
        int nsite = N * 64 * 128;
        lif_seq_kernel<<<(nsite + 255) / 256, 256>>>(conv, bufA, inv, shift, nsite, 128);
    }

    // ---- Layer 6 ----
    g6<<<M * 64 / 128, 256, smg56>>>(bufA, wp6, b[5], conv);
    run_bn(conv, (long)M * 64, 128, gm[5], be[5], sum, sumsq, inv, shift);
    {
        int nsite = N * 64 * 128;
        lif_seq_kernel<<<(nsite + 255) / 256, 256>>>(conv, bufB, inv, shift, nsite, 128);
    }
    {
        int n_out = M * 128 * 4 * 4;
        pool_nhwc<<<(n_out + 255) / 256, 256>>>(bufB, bufA, n_out, 4, 4, 128);
    }

    // ---- fc1 + LIF (input: NHWC-flatten [1024,2048] with permuted weights) ----
    fc1_kernel<<<32, 256>>>(bufA, wfc, fc1_b, conv);
    {
        int nsite = N * 128;
        lif_seq_kernel<<<(nsite + 255) / 256, 256>>>(conv, bufB, (const float*)0, (const float*)0,
                                                     nsite, 1);
    }

    // ---- fc2 + LIF + mean ----
    fc2_lif_mean_kernel<<<N, 320>>>(bufB, fc2_w, fc2_b, out);
}

// round 5
// speedup vs baseline: 2.9696x; 1.3437x over previous
#include <cuda_runtime.h>
#include <math.h>
#include <stdint.h>

// ---------------- static scratch (no allocations allowed) ----------------
__device__ float g_bufA[33554432];
__device__ float g_bufB[33554432];
__device__ float g_conv[33554432];
__device__ float g_wpk[1048576];
__device__ double g_sum[768];
__device__ double g_sumsq[768];

// ---------------- weight packing into mma-fragment order ----------------
// Layout: [chunk ch = tap*CCH + c32][k8 step s:4][tile j:COUT/8][lane:32][4]
// lane -> (g = lane>>2, t = lane&3); 4 floats = {b0hi, b1hi, b0lo, b1lo}
__global__ void pack_w_kernel(const float* __restrict__ w, float* __restrict__ bpk,
                              int CIN, int COUT) {
    int total = 18 * CIN * COUT;
    int idx = blockIdx.x * 256 + threadIdx.x;
    if (idx >= total) return;
    int f    = idx & 3;
    int lane = (idx >> 2) & 31;
    int j    = (idx >> 7) % (COUT / 8);
    int s    = (idx / (32 * COUT)) & 3;
    int ch   = idx / (128 * COUT);
    int g = lane >> 2, t = lane & 3;
    int CCH = CIN / 32;
    int tap = ch / CCH, c32 = ch % CCH;
    int n  = 8 * j + g;
    int kk = s * 8 + t + ((f & 1) ? 4 : 0);
    int ci = c32 * 32 + kk;
    float v = w[((size_t)n * CIN + ci) * 9 + tap];
    uint32_t hb;
    asm("cvt.rna.tf32.f32 %0, %1;" : "=r"(hb) : "f"(v));
    float hi = __uint_as_float(hb);
    bpk[idx] = (f >> 1) ? (v - hi) : hi;
}

// fc1 weight permutation: NCHW-flatten -> NHWC-flatten of the [128,4,4] map
__global__ void permute_fc1_kernel(const float* __restrict__ w, float* __restrict__ wp) {
    int idx = blockIdx.x * 256 + threadIdx.x;
    if (idx >= 128 * 2048) return;
    int o = idx / 2048, k = idx % 2048;   // k = yx*128 + c
    int c = k % 128, yx = k / 128;
    wp[idx] = w[o * 2048 + c * 16 + yx];
}

__global__ void zero_stats_all(double* s, double* s2) {
    int i = blockIdx.x * 256 + threadIdx.x;
    if (i < 768) { s[i] = 0.0; s2[i] = 0.0; }
}

// ---------------- mma.sync tf32 implicit GEMM 3x3 conv (NHWC) + fused BN stats ----------------
template<int CIN, int COUT, int H, int W>
__global__ __launch_bounds__(256) void conv_mma(const float* __restrict__ in,
                                                const float* __restrict__ bpk,
                                                const float* __restrict__ bias,
                                                float* __restrict__ out,
                                                double* __restrict__ dsum,
                                                double* __restrict__ dsumsq)
{
    constexpr int HW = H * W;
    constexpr int CCH = CIN / 32;
    constexpr int NCH = 9 * CCH;
    constexpr int NTILE = COUT / 8;
    constexpr int A_FLOATS = 128 * 36;
    constexpr int B_FLOATS = 64 * COUT;

    extern __shared__ float smem[];
    float*  As  = smem;
    float4* Bs4 = (float4*)(smem + A_FLOATS);
    float*  Ss  = smem + A_FLOATS + B_FLOATS;   // [2*COUT] stats partials

    const int tid  = threadIdx.x;
    const int wid  = tid >> 5;
    const int lane = tid & 31;
    const int g = lane >> 2, t = lane & 3;
    const int p0 = blockIdx.x * 128;

    if (tid < 2 * COUT) Ss[tid] = 0.f;

    float acc[NTILE][4];
    #pragma unroll
    for (int j = 0; j < NTILE; j++)
        #pragma unroll
        for (int q = 0; q < 4; q++) acc[j][q] = 0.f;

    for (int ch = 0; ch < NCH; ch++) {
        if (ch > 0) __syncthreads();
        // ---- load A chunk: 128 pixels x 32 channels (im2col gather) ----
        {
            int tap = ch / CCH, c32 = ch % CCH;
            int ky = tap / 3 - 1, kx = tap % 3 - 1;
            #pragma unroll
            for (int it = 0; it < 4; it++) {
                int lin = it * 256 + tid;
                int ml = lin >> 3, j4 = lin & 7;
                int P = p0 + ml;
                int img = P / HW, pix = P % HW;
                int y = pix / W, x = pix % W;
                int yy = y + ky, xx = x + kx;
                float4 v = make_float4(0.f, 0.f, 0.f, 0.f);
                if ((unsigned)yy < (unsigned)H && (unsigned)xx < (unsigned)W)
                    v = *(const float4*)&in[(((size_t)img * H + yy) * W + xx) * CIN + c32 * 32 + j4 * 4];
                *(float4*)&As[ml * 36 + j4 * 4] = v;
            }
        }
        // ---- load B chunk (fragment-ordered, linear copy) ----
        {
            const float4* src = (const float4*)(bpk + (size_t)ch * B_FLOATS);
            constexpr int NV = B_FLOATS / 4;
            #pragma unroll
            for (int i = tid; i < NV; i += 256) Bs4[i] = src[i];
        }
        __syncthreads();

        // ---- compute: 4 k8 steps ----
        const int m = wid * 16;
        #pragma unroll
        for (int s = 0; s < 4; s++) {
            uint32_t a0 = __float_as_uint(As[(m + g) * 36 + s * 8 + t]);
            uint32_t a1 = __float_as_uint(As[(m + 8 + g) * 36 + s * 8 + t]);
            uint32_t a2 = __float_as_uint(As[(m + g) * 36 + s * 8 + t + 4]);
            uint32_t a3 = __float_as_uint(As[(m + 8 + g) * 36 + s * 8 + t + 4]);
            #pragma unroll
            for (int j = 0; j < NTILE; j++) {
                float4 bf = Bs4[(s * NTILE + j) * 32 + lane];
                uint32_t b0h = __float_as_uint(bf.x), b1h = __float_as_uint(bf.y);
                uint32_t b0l = __float_as_uint(bf.z), b1l = __float_as_uint(bf.w);
                asm("mma.sync.aligned.m16n8k8.row.col.f32.tf32.tf32.f32 "
                    "{%0,%1,%2,%3}, {%4,%5,%6,%7}, {%8,%9}, {%0,%1,%2,%3};"
                    : "+f"(acc[j][0]), "+f"(acc[j][1]), "+f"(acc[j][2]), "+f"(acc[j][3])
                    : "r"(a0), "r"(a1), "r"(a2), "r"(a3), "r"(b0h), "r"(b1h));
                asm("mma.sync.aligned.m16n8k8.row.col.f32.tf32.tf32.f32 "
                    "{%0,%1,%2,%3}, {%4,%5,%6,%7}, {%8,%9}, {%0,%1,%2,%3};"
                    : "+f"(acc[j][0]), "+f"(acc[j][1]), "+f"(acc[j][2]), "+f"(acc[j][3])
                    : "r"(a0), "r"(a1), "r"(a2), "r"(a3), "r"(b0l), "r"(b1l));
            }
        }
    }

    // ---- epilogue: bias + store (NHWC) + fused BN partial stats ----
    const int row0 = p0 + wid * 16 + g;
    #pragma unroll
    for (int j = 0; j < NTILE; j++) {
        int col = 8 * j + 2 * t;
        float2 bb = *(const float2*)&bias[col];
        float2 v0 = make_float2(acc[j][0] + bb.x, acc[j][1] + bb.y);
        float2 v1 = make_float2(acc[j][2] + bb.x, acc[j][3] + bb.y);
        *(float2*)&out[(size_t)row0 * COUT + col] = v0;
        *(float2*)&out[(size_t)(row0 + 8) * COUT + col] = v1;
        // per-column partial sums over this warp's 16 rows
        float s0 = v0.x + v1.x, s1 = v0.y + v1.y;
        float q0 = v0.x * v0.x + v1.x * v1.x, q1 = v0.y * v0.y + v1.y * v1.y;
        #pragma unroll
        for (int off = 4; off < 32; off <<= 1) {
            s0 += __shfl_xor_sync(0xffffffffu, s0, off);
            s1 += __shfl_xor_sync(0xffffffffu, s1, off);
            q0 += __shfl_xor_sync(0xffffffffu, q0, off);
            q1 += __shfl_xor_sync(0xffffffffu, q1, off);
        }
        if (g == 0) {
            atomicAdd(&Ss[col], s0);
            atomicAdd(&Ss[col + 1], s1);
            atomicAdd(&Ss[COUT + col], q0);
            atomicAdd(&Ss[COUT + col + 1], q1);
        }
    }
    __syncthreads();
    if (tid < COUT) {
        atomicAdd(&dsum[tid], (double)Ss[tid]);
        atomicAdd(&dsumsq[tid], (double)Ss[COUT + tid]);
    }
}

// ---------------- layer-1 direct fp32 conv (CIN=3), NCHW in -> NHWC out ----------------
template<int CIN, int COUT, int H, int W, int RPB, int CO_BLK, int CCH, int NT>
__global__ __launch_bounds__(NT) void conv3x3_kernel(
    const float* __restrict__ in, const float* __restrict__ wgt,
    const float* __restrict__ bias, float* __restrict__ out)
{
    constexpr int TH = RPB + 2, TW = W + 2;
    constexpr int IN_FLOATS = CCH * TH * TW;
    constexpr int NCG = CO_BLK / 8;
    extern __shared__ float smemf[];
    float* s_in = smemf;
    float* s_w  = smemf + IN_FLOATS;

    const int m = blockIdx.x;
    const int row0 = blockIdx.y * RPB;
    const int cobase = blockIdx.z * CO_BLK;
    const int tid = threadIdx.x;
    const int cg = tid % NCG;
    const int pg = tid / NCG;
    const int r = pg / (W / 4);
    const int c0 = (pg % (W / 4)) * 4;

    float acc[4][8];
    #pragma unroll
    for (int p = 0; p < 4; p++)
        #pragma unroll
        for (int q = 0; q < 8; q++) acc[p][q] = 0.f;

    for (int cb = 0; cb < CIN; cb += CCH) {
        for (int e = tid; e < IN_FLOATS; e += NT) {
            int ci = e / (TH * TW); int rem = e % (TH * TW);
            int rr = rem / TW, cc = rem % TW;
            int gr = row0 - 1 + rr, gc = cc - 1;
            float v = 0.f;
            if (gr >= 0 && gr < H && gc >= 0 && gc < W)
                v = in[(((size_t)m * CIN + cb + ci) * H + gr) * W + gc];
            s_in[e] = v;
        }
        constexpr int W_FLOATS = CCH * 9 * CO_BLK;
        for (int e = tid; e < W_FLOATS; e += NT) {
            int co = e % CO_BLK; int t9 = (e / CO_BLK) % 9; int ci = e / (9 * CO_BLK);
            s_w[e] = wgt[(((size_t)(cobase + co)) * CIN + cb + ci) * 9 + t9];
        }
        __syncthreads();

        for (int ci = 0; ci < CCH; ci++) {
            const float* tin = s_in + ci * TH * TW;
            const float* tw  = s_w  + ci * 9 * CO_BLK + cg * 8;
            #pragma unroll
            for (int kh = 0; kh < 3; kh++) {
                float xv[6];
                const float* rowp = tin + (r + kh) * TW + c0;
                #pragma unroll
                for (int j = 0; j < 6; j++) xv[j] = rowp[j];
                #pragma unroll
                for (int kw = 0; kw < 3; kw++) {
                    const float4 w0 = *(const float4*)(tw + (kh * 3 + kw) * CO_BLK);
                    const float4 w1 = *(const float4*)(tw + (kh * 3 + kw) * CO_BLK + 4);
                    float wv[8] = {w0.x, w0.y, w0.z, w0.w, w1.x, w1.y, w1.z, w1.w};
                    #pragma unroll
                    for (int p = 0; p < 4; p++)
                        #pragma unroll
                        for (int q = 0; q < 8; q++)
                            acc[p][q] += xv[kw + p] * wv[q];
                }
            }
        }
        __syncthreads();
    }

    float bq[8];
    #pragma unroll
    for (int q = 0; q < 8; q++) bq[q] = bias[cobase + cg * 8 + q];
    #pragma unroll
    for (int p = 0; p < 4; p++) {
        float* op = &out[(((size_t)m * H + row0 + r) * W + c0 + p) * COUT + cobase + cg * 8];
        float4 v0 = make_float4(acc[p][0] + bq[0], acc[p][1] + bq[1], acc[p][2] + bq[2], acc[p][3] + bq[3]);
        float4 v1 = make_float4(acc[p][4] + bq[4], acc[p][5] + bq[5], acc[p][6] + bq[6], acc[p][7] + bq[7]);
        *(float4*)op = v0;
        *(float4*)(op + 4) = v1;
    }
}

// ---------------- BN stats for layer 1 (NHWC) ----------------
__global__ void bn_stats_nhwc(const float* __restrict__ x, long npix, int C,
                              double* __restrict__ sum, double* __restrict__ sumsq)
{
    int tid = threadIdx.x;
    int c = tid % C, g = tid / C;
    int G = blockDim.x / C;
    double s = 0.0, s2 = 0.0;
    for (long p = (long)blockIdx.x * G + g; p < npix; p += (long)gridDim.x * G) {
        float v = x[p * C + c];
        s += v; s2 += (double)v * (double)v;
    }
    __shared__ double sh[256], sh2[256];
    sh[tid] = s; sh2[tid] = s2;
    __syncthreads();
    for (int st = G / 2; st > 0; st >>= 1) {
        if (g < st) { sh[tid] += sh[tid + st * C]; sh2[tid] += sh2[tid + st * C]; }
        __syncthreads();
    }
    if (g == 0) {
        atomicAdd(sum + c, sh[tid]);
        atomicAdd(sumsq + c, sh2[tid]);
    }
}

// ---------------- inline BN finalize helper ----------------
__device__ __forceinline__ void bn_coeffs(const double* sum, const double* sumsq, double icnt,
                                          const float* gam, const float* bet, int c,
                                          float& iv, float& sh)
{
    double mu = sum[c] * icnt;
    double var = sumsq[c] * icnt - mu * mu;
    iv = gam[c] / sqrtf((float)var + 1e-5f);
    sh = bet[c] - (float)mu * iv;
}

// ---------------- LIF (TAU=2, th=1, hard reset), NHWC, finalize inline ----------------
__global__ void lif_seq_kernel(const float* __restrict__ x, float* __restrict__ s,
                               const double* __restrict__ sum, const double* __restrict__ sumsq,
                               double icnt, const float* __restrict__ gam, const float* __restrict__ bet,
                               int nsite, int C)
{
    int idx = blockIdx.x * blockDim.x + threadIdx.x;
    if (idx >= nsite) return;
    float iv = 1.f, sh = 0.f;
    if (gam) bn_coeffs(sum, sumsq, icnt, gam, bet, idx % C, iv, sh);
    float v = 0.f;
    #pragma unroll
    for (int t = 0; t < 8; t++) {
        float y = x[(size_t)t * nsite + idx] * iv + sh;
        v = 0.5f * (v + y);
        float sp = (v >= 1.0f) ? 1.0f : 0.0f;
        s[(size_t)t * nsite + idx] = sp;
        v *= (1.0f - sp);
    }
}

// Layer-1 LIF: input identical across T (read once)
__global__ void lif_bcast_kernel(const float* __restrict__ x, float* __restrict__ s,
                                 const double* __restrict__ sum, const double* __restrict__ sumsq,
                                 double icnt, const float* __restrict__ gam, const float* __restrict__ bet,
                                 int nsite, int C)
{
    int idx = blockIdx.x * blockDim.x + threadIdx.x;
    if (idx >= nsite) return;
    float iv, sh;
    bn_coeffs(sum, sumsq, icnt, gam, bet, idx % C, iv, sh);
    float y = x[idx] * iv + sh;
    float v = 0.f;
    #pragma unroll
    for (int t = 0; t < 8; t++) {
        v = 0.5f * (v + y);
        float sp = (v >= 1.0f) ? 1.0f : 0.0f;
        s[(size_t)t * nsite + idx] = sp;
        v *= (1.0f - sp);
    }
}

// ---------------- LIF + 2x2 maxpool fused (layers 2,4,6), NHWC ----------------
// x: [T][Nimg][Hi][Wi][C] (Nimg = images per timestep), s out: [T][Nimg][OH][OW][C]
__global__ void lif_pool_kernel(const float* __restrict__ x, float* __restrict__ s,
                                const double* __restrict__ sum, const double* __restrict__ sumsq,
                                double icnt, const float* __restrict__ gam, const float* __restrict__ bet,
                                int nout, int C, int OH, int OW, int Nimg)
{
    int idx = blockIdx.x * blockDim.x + threadIdx.x;
    if (idx >= nout) return;
    int c = idx % C;
    int r = idx / C;
    int ox = r % OW; r /= OW;
    int oy = r % OH;
    int n = r / OH;
    float iv, sh;
    bn_coeffs(sum, sumsq, icnt, gam, bet, c, iv, sh);
    int Wi = OW * 2, Hi = OH * 2;
    size_t base = (((size_t)n * Hi + 2 * oy) * Wi + 2 * ox) * C + c;
    size_t tstr = (size_t)Nimg * Hi * Wi * C;
    size_t rstr = (size_t)Wi * C;
    float v0 = 0.f, v1 = 0.f, v2 = 0.f, v3 = 0.f;
    #pragma unroll
    for (int t = 0; t < 8; t++) {
        const float* p = x + (size_t)t * tstr + base;
        float y0 = p[0] * iv + sh;
        float y1 = p[C] * iv + sh;
        float y2 = p[rstr] * iv + sh;
        float y3 = p[rstr + C] * iv + sh;
        v0 = 0.5f * (v0 + y0); float s0 = (v0 >= 1.0f) ? 1.0f : 0.0f; v0 *= (1.0f - s0);
        v1 = 0.5f * (v1 + y1); float s1 = (v1 >= 1.0f) ? 1.0f : 0.0f; v1 *= (1.0f - s1);
        v2 = 0.5f * (v2 + y2); float s2 = (v2 >= 1.0f) ? 1.0f : 0.0f; v2 *= (1.0f - s2);
        v3 = 0.5f * (v3 + y3); float s3 = (v3 >= 1.0f) ? 1.0f : 0.0f; v3 *= (1.0f - s3);
        s[(size_t)t * nout + idx] = fmaxf(fmaxf(s0, s1), fmaxf(s2, s3));
    }
}

// ---------------- fc1: [1024,2048] x [128,2048]^T + bias ----------------
__global__ __launch_bounds__(256) void fc1_kernel(const float* __restrict__ A,
                                                  const float* __restrict__ Bw,
                                                  const float* __restrict__ bias,
                                                  float* __restrict__ C)
{
    __shared__ float As[32][64];
    __shared__ float Bs[64][132];
    int tid = threadIdx.x;
    int r0 = blockIdx.x * 32;
    int tx = tid % 32, ty = tid / 32;
    float acc[4][4];
    #pragma unroll
    for (int i = 0; i < 4; i++)
        #pragma unroll
        for (int j = 0; j < 4; j++) acc[i][j] = 0.f;

    for (int k0 = 0; k0 < 2048; k0 += 64) {
        #pragma unroll
        for (int l = 0; l < 8; l++) {
            int e = tid + l * 256;
            int rr = e >> 6, kk = e & 63;
            As[rr][kk] = A[(size_t)(r0 + rr) * 2048 + k0 + kk];
        }
        #pragma unroll
        for (int l = 0; l < 32; l++) {
            int e = tid + l * 256;
            int kk = e & 63, oo = e >> 6;
            Bs[kk][oo] = Bw[(size_t)oo * 2048 + k0 + kk];
        }
        __syncthreads();
        for (int kk = 0; kk < 64; kk++) {
            float a[4];
            #pragma unroll
            for (int i = 0; i < 4; i++) a[i] = As[ty * 4 + i][kk];
            float4 bv = *(const float4*)&Bs[kk][tx * 4];
            float b[4] = {bv.x, bv.y, bv.z, bv.w};
            #pragma unroll
            for (int i = 0; i < 4; i++)
                #pragma unroll
                for (int j = 0; j < 4; j++)
                    acc[i][j] += a[i] * b[j];
        }
        __syncthreads();
    }
    #pragma unroll
    for (int i = 0; i < 4; i++)
        #pragma unroll
        for (int j = 0; j < 4; j++)
            C[(size_t)(r0 + ty * 4 + i) * 128 + tx * 4 + j] = acc[i][j] + bias[tx * 4 + j];
}

// ---------------- fc2 + LIF + mean over T, fused ----------------
__global__ __launch_bounds__(320) void fc2_lif_mean_kernel(const float* __restrict__ h,
                                                           const float* __restrict__ w2,
                                                           const float* __restrict__ b2,
                                                           float* __restrict__ out)
{
    int n = blockIdx.x;
    int o = threadIdx.x / 32;
    int lane = threadIdx.x % 32;
    float w[4];
    #pragma unroll
    for (int j = 0; j < 4; j++) w[j] = w2[o * 128 + lane * 4 + j];
    float bb = b2[o];
    float v = 0.f, accum = 0.f;
    #pragma unroll
    for (int t = 0; t < 8; t++) {
        const float* hp = h + (size_t)t * 16384 + (size_t)n * 128 + lane * 4;
        float p = 0.f;
        #pragma unroll
        for (int j = 0; j < 4; j++) p += hp[j] * w[j];
        #pragma unroll
        for (int off = 16; off > 0; off >>= 1)
            p += __shfl_xor_sync(0xffffffffu, p, off);
        float y = p + bb;
        v = 0.5f * (v + y);
        float sp = (v >= 1.0f) ? 1.0f : 0.0f;
        v *= (1.0f - sp);
        accum += sp;
    }
    if (lane == 0) out[n * 10 + o] = accum * 0.125f;
}

// ---------------- host orchestration ----------------
extern "C" void kernel_launch(void* const* d_in, const int* in_sizes, int n_in,
                              void* d_out, int out_size)
{
    const float* x = (const float*)d_in[0];
    const float* w[6]; const float* b[6]; const float* gm[6]; const float* be[6];
    for (int i = 0; i < 6; i++) {
        w[i]  = (const float*)d_in[1 + 4 * i];
        b[i]  = (const float*)d_in[2 + 4 * i];
        gm[i] = (const float*)d_in[3 + 4 * i];
        be[i] = (const float*)d_in[4 + 4 * i];
    }
    const float* fc1_w = (const float*)d_in[25];
    const float* fc1_b = (const float*)d_in[26];
    const float* fc2_w = (const float*)d_in[27];
    const float* fc2_b = (const float*)d_in[28];
    float* out = (float*)d_out;

    float *bufA, *bufB, *conv, *wpk;
    double *sum, *sumsq;
    cudaGetSymbolAddress((void**)&bufA, g_bufA);
    cudaGetSymbolAddress((void**)&bufB, g_bufB);
    cudaGetSymbolAddress((void**)&conv, g_conv);
    cudaGetSymbolAddress((void**)&wpk, g_wpk);
    cudaGetSymbolAddress((void**)&sum, g_sum);
    cudaGetSymbolAddress((void**)&sumsq, g_sumsq);

    // packed-weight offsets (floats): 18*CIN*COUT each
    float* wp2 = wpk;             // 18432
    float* wp3 = wpk + 18432;     // 36864
    float* wp4 = wpk + 55296;     // 73728
    float* wp5 = wpk + 129024;    // 147456
    float* wp6 = wpk + 276480;    // 294912
    float* wfc = wpk + 571392;    // 262144

    // kernel instances + smem attrs
    auto k1 = conv3x3_kernel<3, 32, 32, 32, 8, 32, 3, 256>;
    const int sm1 = (3 * 10 * 34 + 3 * 9 * 32) * 4;

    auto g2 = conv_mma<32, 32, 32, 32>;
    auto g3 = conv_mma<32, 64, 16, 16>;
    auto g4 = conv_mma<64, 64, 16, 16>;
    auto g5 = conv_mma<64, 128, 8, 8>;
    auto g6 = conv_mma<128, 128, 8, 8>;
    const int smg2  = (128 * 36 + 64 * 32 + 64) * 4;     // A + B + stats
    const int smg34 = (128 * 36 + 64 * 64 + 128) * 4;
    const int smg56 = (128 * 36 + 64 * 128 + 256) * 4;
    cudaFuncSetAttribute((const void*)g2, cudaFuncAttributeMaxDynamicSharedMemorySize, smg2);
    cudaFuncSetAttribute((const void*)g3, cudaFuncAttributeMaxDynamicSharedMemorySize, smg34);
    cudaFuncSetAttribute((const void*)g4, cudaFuncAttributeMaxDynamicSharedMemorySize, smg34);
    cudaFuncSetAttribute((const void*)g5, cudaFuncAttributeMaxDynamicSharedMemorySize, smg56);
    cudaFuncSetAttribute((const void*)g6, cudaFuncAttributeMaxDynamicSharedMemorySize, smg56);

    const int N = 128, M = 1024;  // M = T*N; N = images per timestep
    double* s1 = sum;        double* q1 = sumsq;
    double* s2 = sum + 128;  double* q2 = sumsq + 128;
    double* s3 = sum + 256;  double* q3 = sumsq + 256;
    double* s4 = sum + 384;  double* q4 = sumsq + 384;
    double* s5 = sum + 512;  double* q5 = sumsq + 512;
    double* s6 = sum + 640;  double* q6 = sumsq + 640;

    // launch 0: zero all BN accumulators
    zero_stats_all<<<3, 256>>>(sum, sumsq);
    // launch 1: layer-1 conv (input identical across T: conv once over N), NHWC out
    k1<<<dim3(N, 4, 1), 256, sm1>>>(x, w[0], b[0], conv);
    // launch 2: pack layer-2 weights
    pack_w_kernel<<<(18 * 32 * 32 + 255) / 256, 256>>>(w[1], wp2, 32, 32);
    // launch 3: layer-1 BN stats
    bn_stats_nhwc<<<512, 256>>>(conv, (long)N * 1024, 32, s1, q1);
    // launch 4: layer-1 LIF (broadcast over T), finalize inline
    {
        int nsite = N * 1024 * 32;
        lif_bcast_kernel<<<(nsite + 255) / 256, 256>>>(conv, bufA, s1, q1,
            1.0 / ((double)N * 1024), gm[0], be[0], nsite, 32);
    }
    // launch 5: layer-2 conv (ncu capture target)
    g2<<<M * 1024 / 128, 256, smg2>>>(bufA, wp2, b[1], conv, s2, q2);
    // launch 6: layer-2 LIF+pool -> [T][N,16,16,32]
    {
        int nout = N * 16 * 16 * 32;
        lif_pool_kernel<<<(nout + 255) / 256, 256>>>(conv, bufB, s2, q2,
            1.0 / ((double)M * 1024), gm[1], be[1], nout, 32, 16, 16, N);
    }
    pack_w_kernel<<<(18 * 32 * 64 + 255) / 256, 256>>>(w[2], wp3, 32, 64);
    // layer 3
    g3<<<M * 256 / 128, 256, smg34>>>(bufB, wp3, b[2], conv, s3, q3);
    {
        int nsite = N * 256 * 64;
        lif_seq_kernel<<<(nsite + 255) / 256, 256>>>(conv, bufA, s3, q3,
            1.0 / ((double)M * 256), gm[2], be[2], nsite, 64);
    }
    pack_w_kernel<<<(18 * 64 * 64 + 255) / 256, 256>>>(w[3], wp4, 64, 64);
    // layer 4 (+pool)
    g4<<<M * 256 / 128, 256, smg34>>>(bufA, wp4, b[3], conv, s4, q4);
    {
        int nout = N * 8 * 8 * 64;
        lif_pool_kernel<<<(nout + 255) / 256, 256>>>(conv, bufB, s4, q4,
            1.0 / ((double)M * 256), gm[3], be[3], nout, 64, 8, 8, N);
    }
    pack_w_kernel<<<(18 * 64 * 128 + 255) / 256, 256>>>(w[4], wp5, 64, 128);
    // layer 5
    g5<<<M * 64 / 128, 256, smg56>>>(bufB, wp5, b[4], conv, s5, q5);
    {
        int nsite = N * 64 * 128;
        lif_seq_kernel<<<(nsite + 255) / 256, 256>>>(conv, bufA, s5, q5,
            1.0 / ((double)M * 64), gm[4], be[4], nsite, 128);
    }
    pack_w_kernel<<<(18 * 128 * 128 + 255) / 256, 256>>>(w[5], wp6, 128, 128);
    // layer 6 (+pool) -> [T][N,4,4,128] == NHWC flatten [1024,2048]
    g6<<<M * 64 / 128, 256, smg56>>>(bufA, wp6, b[5], conv, s6, q6);
    {
        int nout = N * 4 * 4 * 128;
        lif_pool_kernel<<<(nout + 255) / 256, 256>>>(conv, bufB, s6, q6,
            1.0 / ((double)M * 64), gm[5], be[5], nout, 128, 4, 4, N);
    }
    // fc1 (+permuted weights) + LIF
    permute_fc1_kernel<<<(128 * 2048 + 255) / 256, 256>>>(fc1_w, wfc);
    fc1_kernel<<<32, 256>>>(bufB, wfc, fc1_b, conv);
    {
        int nsite = N * 128;
        lif_seq_kernel<<<(nsite + 255) / 256, 256>>>(conv, bufA, (const double*)0, (const double*)0,
            0.0, (const float*)0, (const float*)0, nsite, 1);
    }
    // fc2 + LIF + mean
    fc2_lif_mean_kernel<<<N, 320>>>(bufA, fc2_w, fc2_b, out);
}

// round 6
// speedup vs baseline: 3.4566x; 1.1640x over previous
#include <cuda_runtime.h>
#include <math.h>
#include <stdint.h>

// ---------------- static scratch (no allocations allowed) ----------------
__device__ float g_bufA[33554432];
__device__ float g_bufB[33554432];
__device__ float g_conv[33554432];
__device__ float g_wpk[1048576];
__device__ double g_sum[768];
__device__ double g_sumsq[768];

__device__ __forceinline__ uint32_t smem_u32(const void* p) {
    uint32_t a;
    asm("{ .reg .u64 t; cvta.to.shared.u64 t, %1; cvt.u32.u64 %0, t; }" : "=r"(a) : "l"(p));
    return a;
}
__device__ __forceinline__ void cp_async16(uint32_t dst, const void* src, bool ok) {
    int sz = ok ? 16 : 0;
    asm volatile("cp.async.cg.shared.global [%0], [%1], 16, %2;" :: "r"(dst), "l"(src), "r"(sz));
}
__device__ __forceinline__ void cp_commit() { asm volatile("cp.async.commit_group;"); }
__device__ __forceinline__ void cp_wait1() { asm volatile("cp.async.wait_group 1;"); }
__device__ __forceinline__ void cp_wait0() { asm volatile("cp.async.wait_group 0;"); }

// ---------------- prep: zero stats + pack all conv weights + permute fc1 ----------------
// pack layout: [chunk ch = tap*CCH + c32][k8 step s:4][tile j:COUT/8][lane:32][4]
// lane -> (g = lane>>2, t = lane&3); 4 floats = {b0hi, b1hi, b0lo, b1lo}
__device__ __forceinline__ void pack_one(const float* __restrict__ w, float* __restrict__ bpk,
                                         int CIN, int COUT, int idx) {
    int f    = idx & 3;
    int lane = (idx >> 2) & 31;
    int j    = (idx >> 7) % (COUT / 8);
    int s    = (idx / (32 * COUT)) & 3;
    int ch   = idx / (128 * COUT);
    int g = lane >> 2, t = lane & 3;
    int CCH = CIN / 32;
    int tap = ch / CCH, c32 = ch % CCH;
    int n  = 8 * j + g;
    int kk = s * 8 + t + ((f & 1) ? 4 : 0);
    int ci = c32 * 32 + kk;
    float v = w[((size_t)n * CIN + ci) * 9 + tap];
    uint32_t hb;
    asm("cvt.rna.tf32.f32 %0, %1;" : "=r"(hb) : "f"(v));
    float hi = __uint_as_float(hb);
    bpk[idx] = (f >> 1) ? (v - hi) : hi;
}

__global__ void prep_kernel(const float* __restrict__ w2, const float* __restrict__ w3,
                            const float* __restrict__ w4, const float* __restrict__ w5,
                            const float* __restrict__ w6, const float* __restrict__ fc1w,
                            float* __restrict__ wpk, double* __restrict__ sum, double* __restrict__ sumsq)
{
    int idx = blockIdx.x * 256 + threadIdx.x;
    if (idx < 768) { sum[idx] = 0.0; sumsq[idx] = 0.0; }
    if (idx < 18432)                        pack_one(w2, wpk,          32,  32, idx);
    else if (idx < 55296)                   pack_one(w3, wpk + 18432,  32,  64, idx - 18432);
    else if (idx < 129024)                  pack_one(w4, wpk + 55296,  64,  64, idx - 55296);
    else if (idx < 276480)                  pack_one(w5, wpk + 129024, 64, 128, idx - 129024);
    else if (idx < 571392)                  pack_one(w6, wpk + 276480, 128, 128, idx - 276480);
    else if (idx < 833536) {
        int i = idx - 571392;                // fc1: NCHW-flatten -> NHWC-flatten
        int o = i / 2048, k = i % 2048;      // k = yx*128 + c
        int c = k % 128, yx = k / 128;
        wpk[571392 + i] = fc1w[o * 2048 + c * 16 + yx];
    }
}

// ---------------- mma.sync tf32 implicit GEMM 3x3 conv (NHWC), cp.async double-buffered ----------------
template<int CIN, int COUT, int H, int W>
__global__ __launch_bounds__(256) void conv_mma(const float* __restrict__ in,
                                                const float* __restrict__ bpk,
                                                const float* __restrict__ bias,
                                                float* __restrict__ out,
                                                double* __restrict__ dsum,
                                                double* __restrict__ dsumsq)
{
    constexpr int HW = H * W;
    constexpr int CCH = CIN / 32;
    constexpr int NCH = 9 * CCH;
    constexpr int NTILE = COUT / 8;
    constexpr int A_FLOATS = 128 * 36;
    constexpr uint32_t A_BYTES = A_FLOATS * 4;
    constexpr int B_FLOATS = 64 * COUT;
    constexpr uint32_t B_BYTES = B_FLOATS * 4;
    constexpr int NB4 = COUT / 16;          // float4s per thread for one B chunk

    extern __shared__ float smem[];
    float* Ss = smem + 2 * A_FLOATS + 2 * B_FLOATS;   // [2*COUT]
    const uint32_t sA = smem_u32(smem);
    const uint32_t sB = sA + 2 * A_BYTES;

    const int tid  = threadIdx.x;
    const int wid  = tid >> 5;
    const int lane = tid & 31;
    const int g = lane >> 2, t = lane & 3;
    const int p0 = blockIdx.x * 128;

    if (tid < 2 * COUT) Ss[tid] = 0.f;

    // precompute per-thread im2col coordinates (4 vec4 elements per thread)
    int my[4], mx[4];
    const float* gbase[4];
    uint32_t dstoff[4];
    const int j4 = tid & 7;
    #pragma unroll
    for (int it = 0; it < 4; it++) {
        int lin = it * 256 + tid;
        int ml = lin >> 3;
        int P = p0 + ml;
        int img = P / HW, pix = P % HW;
        my[it] = pix / W;
        mx[it] = pix % W;
        gbase[it] = in + ((size_t)img * HW) * CIN + j4 * 4;
        dstoff[it] = (uint32_t)(ml * 144 + j4 * 16);
    }

    auto issue = [&](int ch, int buf) {
        int tap = ch / CCH, c32 = ch % CCH;
        int ky = tap / 3 - 1, kx = tap % 3 - 1;
        uint32_t ab = sA + (uint32_t)buf * A_BYTES;
        #pragma unroll
        for (int it = 0; it < 4; it++) {
            int yy = my[it] + ky, xx = mx[it] + kx;
            bool ok = ((unsigned)yy < (unsigned)H) && ((unsigned)xx < (unsigned)W);
            const float* gp = ok ? (gbase[it] + ((size_t)yy * W + xx) * CIN + c32 * 32) : gbase[it];
            cp_async16(ab + dstoff[it], gp, ok);
        }
        const float4* src = (const float4*)(bpk + (size_t)ch * B_FLOATS);
        uint32_t bb = sB + (uint32_t)buf * B_BYTES;
        #pragma unroll
        for (int i = 0; i < NB4; i++) {
            int e = i * 256 + tid;
            cp_async16(bb + (uint32_t)e * 16, src + e, true);
        }
        cp_commit();
    };

    float acc[NTILE][4];
    #pragma unroll
    for (int j = 0; j < NTILE; j++)
        #pragma unroll
        for (int q = 0; q < 4; q++) acc[j][q] = 0.f;

    issue(0, 0);

    const int m = wid * 16;
    for (int ch = 0; ch < NCH; ch++) {
        int buf = ch & 1;
        if (ch + 1 < NCH) { issue(ch + 1, buf ^ 1); cp_wait1(); }
        else              { cp_wait0(); }
        __syncthreads();

        const float*  As  = smem + buf * A_FLOATS;
        const float4* Bs4 = (const float4*)(smem + 2 * A_FLOATS + buf * B_FLOATS);
        #pragma unroll
        for (int s = 0; s < 4; s++) {
            uint32_t a0 = __float_as_uint(As[(m + g) * 36 + s * 8 + t]);
            uint32_t a1 = __float_as_uint(As[(m + 8 + g) * 36 + s * 8 + t]);
            uint32_t a2 = __float_as_uint(As[(m + g) * 36 + s * 8 + t + 4]);
            uint32_t a3 = __float_as_uint(As[(m + 8 + g) * 36 + s * 8 + t + 4]);
            #pragma unroll
            for (int j = 0; j < NTILE; j++) {
                float4 bf = Bs4[(s * NTILE + j) * 32 + lane];
                uint32_t b0h = __float_as_uint(bf.x), b1h = __float_as_uint(bf.y);
                uint32_t b0l = __float_as_uint(bf.z), b1l = __float_as_uint(bf.w);
                asm("mma.sync.aligned.m16n8k8.row.col.f32.tf32.tf32.f32 "
                    "{%0,%1,%2,%3}, {%4,%5,%6,%7}, {%8,%9}, {%0,%1,%2,%3};"
                    : "+f"(acc[j][0]), "+f"(acc[j][1]), "+f"(acc[j][2]), "+f"(acc[j][3])
                    : "r"(a0), "r"(a1), "r"(a2), "r"(a3), "r"(b0h), "r"(b1h));
                asm("mma.sync.aligned.m16n8k8.row.col.f32.tf32.tf32.f32 "
                    "{%0,%1,%2,%3}, {%4,%5,%6,%7}, {%8,%9}, {%0,%1,%2,%3};"
                    : "+f"(acc[j][0]), "+f"(acc[j][1]), "+f"(acc[j][2]), "+f"(acc[j][3])
                    : "r"(a0), "r"(a1), "r"(a2), "r"(a3), "r"(b0l), "r"(b1l));
            }
        }
        __syncthreads();
    }

    // ---- epilogue: bias + store (NHWC) + fused BN partial stats ----
    const int row0 = p0 + wid * 16 + g;
    #pragma unroll
    for (int j = 0; j < NTILE; j++) {
        int col = 8 * j + 2 * t;
        float2 bb = *(const float2*)&bias[col];
        float2 v0 = make_float2(acc[j][0] + bb.x, acc[j][1] + bb.y);
        float2 v1 = make_float2(acc[j][2] + bb.x, acc[j][3] + bb.y);
        *(float2*)&out[(size_t)row0 * COUT + col] = v0;
        *(float2*)&out[(size_t)(row0 + 8) * COUT + col] = v1;
        float s0 = v0.x + v1.x, s1 = v0.y + v1.y;
        float q0 = v0.x * v0.x + v1.x * v1.x, q1 = v0.y * v0.y + v1.y * v1.y;
        #pragma unroll
        for (int off = 4; off < 32; off <<= 1) {
            s0 += __shfl_xor_sync(0xffffffffu, s0, off);
            s1 += __shfl_xor_sync(0xffffffffu, s1, off);
            q0 += __shfl_xor_sync(0xffffffffu, q0, off);
            q1 += __shfl_xor_sync(0xffffffffu, q1, off);
        }
        if (g == 0) {
            atomicAdd(&Ss[col], s0);
            atomicAdd(&Ss[col + 1], s1);
            atomicAdd(&Ss[COUT + col], q0);
            atomicAdd(&Ss[COUT + col + 1], q1);
        }
    }
    __syncthreads();
    if (tid < COUT) {
        atomicAdd(&dsum[tid], (double)Ss[tid]);
        atomicAdd(&dsumsq[tid], (double)Ss[COUT + tid]);
    }
}

// ---------------- layer-1 direct fp32 conv (CIN=3), NCHW in -> NHWC out, fused BN stats ----------------
template<int CIN, int COUT, int H, int W, int RPB, int CO_BLK, int CCH, int NT>
__global__ __launch_bounds__(NT) void conv3x3_kernel(
    const float* __restrict__ in, const float* __restrict__ wgt,
    const float* __restrict__ bias, float* __restrict__ out,
    double* __restrict__ dsum, double* __restrict__ dsumsq)
{
    constexpr int TH = RPB + 2, TW = W + 2;
    constexpr int IN_FLOATS = CCH * TH * TW;
    constexpr int W_FLOATS = CCH * 9 * CO_BLK;
    constexpr int NCG = CO_BLK / 8;
    extern __shared__ float smemf[];
    float* s_in = smemf;
    float* s_w  = smemf + IN_FLOATS;
    float* Ss   = smemf + IN_FLOATS + W_FLOATS;   // [2*COUT]

    const int m = blockIdx.x;
    const int row0 = blockIdx.y * RPB;
    const int cobase = blockIdx.z * CO_BLK;
    const int tid = threadIdx.x;
    const int lane = tid & 31;
    const int cg = tid % NCG;
    const int pg = tid / NCG;
    const int r = pg / (W / 4);
    const int c0 = (pg % (W / 4)) * 4;

    if (tid < 2 * COUT) Ss[tid] = 0.f;

    float acc[4][8];
    #pragma unroll
    for (int p = 0; p < 4; p++)
        #pragma unroll
        for (int q = 0; q < 8; q++) acc[p][q] = 0.f;

    for (int cb = 0; cb < CIN; cb += CCH) {
        for (int e = tid; e < IN_FLOATS; e += NT) {
            int ci = e / (TH * TW); int rem = e % (TH * TW);
            int rr = rem / TW, cc = rem % TW;
            int gr = row0 - 1 + rr, gc = cc - 1;
            float v = 0.f;
            if (gr >= 0 && gr < H && gc >= 0 && gc < W)
                v = in[(((size_t)m * CIN + cb + ci) * H + gr) * W + gc];
            s_in[e] = v;
        }
        for (int e = tid; e < W_FLOATS; e += NT) {
            int co = e % CO_BLK; int t9 = (e / CO_BLK) % 9; int ci = e / (9 * CO_BLK);
            s_w[e] = wgt[(((size_t)(cobase + co)) * CIN + cb + ci) * 9 + t9];
        }
        __syncthreads();

        for (int ci = 0; ci < CCH; ci++) {
            const float* tin = s_in + ci * TH * TW;
            const float* tw  = s_w  + ci * 9 * CO_BLK + cg * 8;
            #pragma unroll
            for (int kh = 0; kh < 3; kh++) {
                float xv[6];
                const float* rowp = tin + (r + kh) * TW + c0;
                #pragma unroll
                for (int j = 0; j < 6; j++) xv[j] = rowp[j];
                #pragma unroll
                for (int kw = 0; kw < 3; kw++) {
                    const float4 w0 = *(const float4*)(tw + (kh * 3 + kw) * CO_BLK);
                    const float4 w1 = *(const float4*)(tw + (kh * 3 + kw) * CO_BLK + 4);
                    float wv[8] = {w0.x, w0.y, w0.z, w0.w, w1.x, w1.y, w1.z, w1.w};
                    #pragma unroll
                    for (int p = 0; p < 4; p++)
                        #pragma unroll
                        for (int q = 0; q < 8; q++)
                            acc[p][q] += xv[kw + p] * wv[q];
                }
            }
        }
        __syncthreads();
    }

    float bq[8];
    #pragma unroll
    for (int q = 0; q < 8; q++) bq[q] = bias[cobase + cg * 8 + q];
    float ssum[8], ssq[8];
    #pragma unroll
    for (int q = 0; q < 8; q++) { ssum[q] = 0.f; ssq[q] = 0.f; }
    #pragma unroll
    for (int p = 0; p < 4; p++) {
        float v[8];
        #pragma unroll
        for (int q = 0; q < 8; q++) {
            v[q] = acc[p][q] + bq[q];
            ssum[q] += v[q];
            ssq[q]  += v[q] * v[q];
        }
        float* op = &out[(((size_t)m * H + row0 + r) * W + c0 + p) * COUT + cobase + cg * 8];
        *(float4*)op       = make_float4(v[0], v[1], v[2], v[3]);
        *(float4*)(op + 4) = make_float4(v[4], v[5], v[6], v[7]);
    }
    // reduce across lanes with same cg (lane%4): offsets 4,8,16
    #pragma unroll
    for (int off = 4; off < 32; off <<= 1)
        #pragma unroll
        for (int q = 0; q < 8; q++) {
            ssum[q] += __shfl_xor_sync(0xffffffffu, ssum[q], off);
            ssq[q]  += __shfl_xor_sync(0xffffffffu, ssq[q], off);
        }
    if (lane < 4) {
        #pragma unroll
        for (int q = 0; q < 8; q++) {
            int chn = cobase + lane * 8 + q;
            atomicAdd(&Ss[chn], ssum[q]);
            atomicAdd(&Ss[COUT + chn], ssq[q]);
        }
    }
    __syncthreads();
    if (tid < COUT) {
        atomicAdd(&dsum[tid], (double)Ss[tid]);
        atomicAdd(&dsumsq[tid], (double)Ss[COUT + tid]);
    }
}

// ---------------- inline BN finalize helper ----------------
__device__ __forceinline__ void bn_coeffs(const double* sum, const double* sumsq, double icnt,
                                          const float* gam, const float* bet, int c,
                                          float& iv, float& sh)
{
    double mu = sum[c] * icnt;
    double var = sumsq[c] * icnt - mu * mu;
    iv = gam[c] / sqrtf((float)var + 1e-5f);
    sh = bet[c] - (float)mu * iv;
}

// ---------------- LIF (TAU=2, th=1, hard reset), NHWC, finalize inline ----------------
__global__ void lif_seq_kernel(const float* __restrict__ x, float* __restrict__ s,
                               const double* __restrict__ sum, const double* __restrict__ sumsq,
                               double icnt, const float* __restrict__ gam, const float* __restrict__ bet,
                               int nsite, int C)
{
    int idx = blockIdx.x * blockDim.x + threadIdx.x;
    if (idx >= nsite) return;
    float iv = 1.f, sh = 0.f;
    if (gam) bn_coeffs(sum, sumsq, icnt, gam, bet, idx % C, iv, sh);
    float v = 0.f;
    #pragma unroll
    for (int t = 0; t < 8; t++) {
        float y = x[(size_t)t * nsite + idx] * iv + sh;
        v = 0.5f * (v + y);
        float sp = (v >= 1.0f) ? 1.0f : 0.0f;
        s[(size_t)t * nsite + idx] = sp;
        v *= (1.0f - sp);
    }
}

// Layer-1 LIF: input identical across T (read once)
__global__ void lif_bcast_kernel(const float* __restrict__ x, float* __restrict__ s,
                                 const double* __restrict__ sum, const double* __restrict__ sumsq,
                                 double icnt, const float* __restrict__ gam, const float* __restrict__ bet,
                                 int nsite, int C)
{
    int idx = blockIdx.x * blockDim.x + threadIdx.x;
    if (idx >= nsite) return;
    float iv, sh;
    bn_coeffs(sum, sumsq, icnt, gam, bet, idx % C, iv, sh);
    float y = x[idx] * iv + sh;
    float v = 0.f;
    #pragma unroll
    for (int t = 0; t < 8; t++) {
        v = 0.5f * (v + y);
        float sp = (v >= 1.0f) ? 1.0f : 0.0f;
        s[(size_t)t * nsite + idx] = sp;
        v *= (1.0f - sp);
    }
}

// ---------------- LIF + 2x2 maxpool fused (layers 2,4,6), NHWC ----------------
// x: [T][Nimg][Hi][Wi][C], s out: [T][Nimg][OH][OW][C]
__global__ void lif_pool_kernel(const float* __restrict__ x, float* __restrict__ s,
                                const double* __restrict__ sum, const double* __restrict__ sumsq,
                                double icnt, const float* __restrict__ gam, const float* __restrict__ bet,
                                int nout, int C, int OH, int OW, int Nimg)
{
    int idx = blockIdx.x * blockDim.x + threadIdx.x;
    if (idx >= nout) return;
    int c = idx % C;
    int r = idx / C;
    int ox = r % OW; r /= OW;
    int oy = r % OH;
    int n = r / OH;
    float iv, sh;
    bn_coeffs(sum, sumsq, icnt, gam, bet, c, iv, sh);
    int Wi = OW * 2, Hi = OH * 2;
    size_t base = (((size_t)n * Hi + 2 * oy) * Wi + 2 * ox) * C + c;
    size_t tstr = (size_t)Nimg * Hi * Wi * C;
    size_t rstr = (size_t)Wi * C;
    float v0 = 0.f, v1 = 0.f, v2 = 0.f, v3 = 0.f;
    #pragma unroll
    for (int t = 0; t < 8; t++) {
        const float* p = x + (size_t)t * tstr + base;
        float y0 = p[0] * iv + sh;
        float y1 = p[C] * iv + sh;
        float y2 = p[rstr] * iv + sh;
        float y3 = p[rstr + C] * iv + sh;
        v0 = 0.5f * (v0 + y0); float s0 = (v0 >= 1.0f) ? 1.0f : 0.0f; v0 *= (1.0f - s0);
        v1 = 0.5f * (v1 + y1); float s1 = (v1 >= 1.0f) ? 1.0f : 0.0f; v1 *= (1.0f - s1);
        v2 = 0.5f * (v2 + y2); float s2 = (v2 >= 1.0f) ? 1.0f : 0.0f; v2 *= (1.0f - s2);
        v3 = 0.5f * (v3 + y3); float s3 = (v3 >= 1.0f) ? 1.0f : 0.0f; v3 *= (1.0f - s3);
        s[(size_t)t * nout + idx] = fmaxf(fmaxf(s0, s1), fmaxf(s2, s3));
    }
}

// ---------------- fc1: [1024,2048] x [128,2048]^T + bias ----------------
__global__ __launch_bounds__(256) void fc1_kernel(const float* __restrict__ A,
                                                  const float* __restrict__ Bw,
                                                  const float* __restrict__ bias,
                                                  float* __restrict__ C)
{
    __shared__ float As[32][64];
    __shared__ float Bs[64][132];
    int tid = threadIdx.x;
    int r0 = blockIdx.x * 32;
    int tx = tid % 32, ty = tid / 32;
    float acc[4][4];
    #pragma unroll
    for (int i = 0; i < 4; i++)
        #pragma unroll
        for (int j = 0; j < 4; j++) acc[i][j] = 0.f;

    for (int k0 = 0; k0 < 2048; k0 += 64) {
        #pragma unroll
        for (int l = 0; l < 8; l++) {
            int e = tid + l * 256;
            int rr = e >> 6, kk = e & 63;
            As[rr][kk] = A[(size_t)(r0 + rr) * 2048 + k0 + kk];
        }
        #pragma unroll
        for (int l = 0; l < 32; l++) {
            int e = tid + l * 256;
            int kk = e & 63, oo = e >> 6;
            Bs[kk][oo] = Bw[(size_t)oo * 2048 + k0 + kk];
        }
        __syncthreads();
        for (int kk = 0; kk < 64; kk++) {
            float a[4];
            #pragma unroll
            for (int i = 0; i < 4; i++) a[i] = As[ty * 4 + i][kk];
            float4 bv = *(const float4*)&Bs[kk][tx * 4];
            float b[4] = {bv.x, bv.y, bv.z, bv.w};
            #pragma unroll
            for (int i = 0; i < 4; i++)
                #pragma unroll
                for (int j = 0; j < 4; j++)
                    acc[i][j] += a[i] * b[j];
        }
        __syncthreads();
    }
    #pragma unroll
    for (int i = 0; i < 4; i++)
        #pragma unroll
        for (int j = 0; j < 4; j++)
            C[(size_t)(r0 + ty * 4 + i) * 128 + tx * 4 + j] = acc[i][j] + bias[tx * 4 + j];
}

// ---------------- fc2 + LIF + mean over T, fused ----------------
__global__ __launch_bounds__(320) void fc2_lif_mean_kernel(const float* __restrict__ h,
                                                           const float* __restrict__ w2,
                                                           const float* __restrict__ b2,
                                                           float* __restrict__ out)
{
    int n = blockIdx.x;
    int o = threadIdx.x / 32;
    int lane = threadIdx.x % 32;
    float w[4];
    #pragma unroll
    for (int j = 0; j < 4; j++) w[j] = w2[o * 128 + lane * 4 + j];
    float bb = b2[o];
    float v = 0.f, accum = 0.f;
    #pragma unroll
    for (int t = 0; t < 8; t++) {
        const float* hp = h + (size_t)t * 16384 + (size_t)n * 128 + lane * 4;
        float p = 0.f;
        #pragma unroll
        for (int j = 0; j < 4; j++) p += hp[j] * w[j];
        #pragma unroll
        for (int off = 16; off > 0; off >>= 1)
            p += __shfl_xor_sync(0xffffffffu, p, off);
        float y = p + bb;
        v = 0.5f * (v + y);
        float sp = (v >= 1.0f) ? 1.0f : 0.0f;
        v *= (1.0f - sp);
        accum += sp;
    }
    if (lane == 0) out[n * 10 + o] = accum * 0.125f;
}

// ---------------- host orchestration ----------------
extern "C" void kernel_launch(void* const* d_in, const int* in_sizes, int n_in,
                              void* d_out, int out_size)
{
    const float* x = (const float*)d_in[0];
    const float* w[6]; const float* b[6]; const float* gm[6]; const float* be[6];
    for (int i = 0; i < 6; i++) {
        w[i]  = (const float*)d_in[1 + 4 * i];
        b[i]  = (const float*)d_in[2 + 4 * i];
        gm[i] = (const float*)d_in[3 + 4 * i];
        be[i] = (const float*)d_in[4 + 4 * i];
    }
    const float* fc1_w = (const float*)d_in[25];
    const float* fc1_b = (const float*)d_in[26];
    const float* fc2_w = (const float*)d_in[27];
    const float* fc2_b = (const float*)d_in[28];
    float* out = (float*)d_out;

    float *bufA, *bufB, *conv, *wpk;
    double *sum, *sumsq;
    cudaGetSymbolAddress((void**)&bufA, g_bufA);
    cudaGetSymbolAddress((void**)&bufB, g_bufB);
    cudaGetSymbolAddress((void**)&conv, g_conv);
    cudaGetSymbolAddress((void**)&wpk, g_wpk);
    cudaGetSymbolAddress((void**)&sum, g_sum);
    cudaGetSymbolAddress((void**)&sumsq, g_sumsq);

    float* wp2 = wpk;             // 18432
    float* wp3 = wpk + 18432;     // 36864
    float* wp4 = wpk + 55296;     // 73728
    float* wp5 = wpk + 129024;    // 147456
    float* wp6 = wpk + 276480;    // 294912
    float* wfc = wpk + 571392;    // 262144

    auto k1 = conv3x3_kernel<3, 32, 32, 32, 8, 32, 3, 256>;
    const int sm1 = (3 * 10 * 34 + 3 * 9 * 32 + 64) * 4;

    auto g2 = conv_mma<32, 32, 32, 32>;
    auto g3 = conv_mma<32, 64, 16, 16>;
    auto g4 = conv_mma<64, 64, 16, 16>;
    auto g5 = conv_mma<64, 128, 8, 8>;
    auto g6 = conv_mma<128, 128, 8, 8>;
    const int smg2  = (2 * 128 * 36 + 2 * 64 * 32 + 64) * 4;    // 53504
    const int smg34 = (2 * 128 * 36 + 2 * 64 * 64 + 128) * 4;   // 70144
    const int smg56 = (2 * 128 * 36 + 2 * 64 * 128 + 256) * 4;  // 103424
    cudaFuncSetAttribute((const void*)g2, cudaFuncAttributeMaxDynamicSharedMemorySize, smg2);
    cudaFuncSetAttribute((const void*)g3, cudaFuncAttributeMaxDynamicSharedMemorySize, smg34);
    cudaFuncSetAttribute((const void*)g4, cudaFuncAttributeMaxDynamicSharedMemorySize, smg34);
    cudaFuncSetAttribute((const void*)g5, cudaFuncAttributeMaxDynamicSharedMemorySize, smg56);
    cudaFuncSetAttribute((const void*)g6, cudaFuncAttributeMaxDynamicSharedMemorySize, smg56);

    const int N = 128, M = 1024;  // M = T*N; N = images per timestep
    double* s1 = sum;        double* q1 = sumsq;
    double* s2 = sum + 128;  double* q2 = sumsq + 128;
    double* s3 = sum + 256;  double* q3 = sumsq + 256;
    double* s4 = sum + 384;  double* q4 = sumsq + 384;
    double* s5 = sum + 512;  double* q5 = sumsq + 512;
    double* s6 = sum + 640;  double* q6 = sumsq + 640;

    // launch 0: prep (zero stats + pack all weights + fc1 permute)
    prep_kernel<<<3257, 256>>>(w[1], w[2], w[3], w[4], w[5], fc1_w, wpk, sum, sumsq);
    // launch 1: layer-1 conv + fused BN stats
    k1<<<dim3(N, 4, 1), 256, sm1>>>(x, w[0], b[0], conv, s1, q1);
    // launch 2: layer-1 LIF (broadcast over T), finalize inline
    {
        int nsite = N * 1024 * 32;
        lif_bcast_kernel<<<(nsite + 255) / 256, 256>>>(conv, bufA, s1, q1,
            1.0 / ((double)N * 1024), gm[0], be[0], nsite, 32);
    }
    // launch 3: layer-2 conv  <-- ncu capture target
    g2<<<M * 1024 / 128, 256, smg2>>>(bufA, wp2, b[1], conv, s2, q2);
    // layer-2 LIF+pool -> [T][N,16,16,32]
    {
        int nout = N * 16 * 16 * 32;
        lif_pool_kernel<<<(nout + 255) / 256, 256>>>(conv, bufB, s2, q2,
            1.0 / ((double)M * 1024), gm[1], be[1], nout, 32, 16, 16, N);
    }
    // layer 3
    g3<<<M * 256 / 128, 256, smg34>>>(bufB, wp3, b[2], conv, s3, q3);
    {
        int nsite = N * 256 * 64;
        lif_seq_kernel<<<(nsite + 255) / 256, 256>>>(conv, bufA, s3, q3,
            1.0 / ((double)M * 256), gm[2], be[2], nsite, 64);
    }
    // layer 4 (+pool)
    g4<<<M * 256 / 128, 256, smg34>>>(bufA, wp4, b[3], conv, s4, q4);
    {
        int nout = N * 8 * 8 * 64;
        lif_pool_kernel<<<(nout + 255) / 256, 256>>>(conv, bufB, s4, q4,
            1.0 / ((double)M * 256), gm[3], be[3], nout, 64, 8, 8, N);
    }
    // layer 5
    g5<<<M * 64 / 128, 256, smg56>>>(bufB, wp5, b[4], conv, s5, q5);
    {
        int nsite = N * 64 * 128;
        lif_seq_kernel<<<(nsite + 255) / 256, 256>>>(conv, bufA, s5, q5,
            1.0 / ((double)M * 64), gm[4], be[4], nsite, 128);
    }
    // layer 6 (+pool) -> [T][N,4,4,128] == NHWC flatten [1024,2048]
    g6<<<M * 64 / 128, 256, smg56>>>(bufA, wp6, b[5], conv, s6, q6);
    {
        int nout = N * 4 * 4 * 128;
        lif_pool_kernel<<<(nout + 255) / 256, 256>>>(conv, bufB, s6, q6,
            1.0 / ((double)M * 64), gm[5], be[5], nout, 128, 4, 4, N);
    }
    // fc1 + LIF
    fc1_kernel<<<32, 256>>>(bufB, wfc, fc1_b, conv);
    {
        int nsite = N * 128;
        lif_seq_kernel<<<(nsite + 255) / 256, 256>>>(conv, bufA, (const double*)0, (const double*)0,
            0.0, (const float*)0, (const float*)0, nsite, 1);
    }
    // fc2 + LIF + mean
    fc2_lif_mean_kernel<<<N, 320>>>(bufA, fc2_w, fc2_b, out);
}